// round 1
// baseline (speedup 1.0000x reference)
#include <cuda_runtime.h>
#include <math.h>

#define SEQ    4096
#define HID    4096
#define NHEADS 32
#define NKV    8
#define HD     128

// Scratch (device globals: allocation-free rule)
__device__ float g_Q[(size_t)NHEADS * SEQ * HD];  // [head][seq][128]
__device__ float g_K[(size_t)NKV    * SEQ * HD];  // [kvhead][seq][128]
__device__ float g_V[(size_t)NKV    * SEQ * HD];
__device__ float g_A[(size_t)SEQ * HID];          // attn out, [seq][head*128]

// ---------------------------------------------------------------------------
// SGEMM: C = A(MxK) * B(NxK)^T, row-major. mode 0: C[row*N+col]
// mode 1: scatter to head-major C[(head*M + row)*128 + d], head=col>>7,d=col&127
// ---------------------------------------------------------------------------
__global__ __launch_bounds__(256) void sgemm_nt(const float* __restrict__ A,
                                                const float* __restrict__ B,
                                                float* __restrict__ C,
                                                int M, int N, int K, int mode)
{
    __shared__ float As[16][128 + 4];
    __shared__ float Bs[16][128 + 4];

    const int tid  = threadIdx.x;
    const int bm   = blockIdx.y * 128;
    const int bn   = blockIdx.x * 128;
    const int lrow = tid >> 2;          // 0..63
    const int lcol = (tid & 3) << 2;    // 0,4,8,12
    const int tr   = tid >> 4;          // 0..15
    const int tc   = tid & 15;          // 0..15

    float acc[8][8];
#pragma unroll
    for (int i = 0; i < 8; i++)
#pragma unroll
        for (int j = 0; j < 8; j++) acc[i][j] = 0.f;

    const float* Ap = A + (size_t)(bm + lrow) * K + lcol;
    const float* Bp = B + (size_t)(bn + lrow) * K + lcol;

    for (int k0 = 0; k0 < K; k0 += 16) {
        float4 a0 = *(const float4*)(Ap + k0);
        float4 a1 = *(const float4*)(Ap + k0 + (size_t)64 * K);
        float4 b0 = *(const float4*)(Bp + k0);
        float4 b1 = *(const float4*)(Bp + k0 + (size_t)64 * K);

        As[lcol + 0][lrow] = a0.x; As[lcol + 1][lrow] = a0.y;
        As[lcol + 2][lrow] = a0.z; As[lcol + 3][lrow] = a0.w;
        As[lcol + 0][lrow + 64] = a1.x; As[lcol + 1][lrow + 64] = a1.y;
        As[lcol + 2][lrow + 64] = a1.z; As[lcol + 3][lrow + 64] = a1.w;
        Bs[lcol + 0][lrow] = b0.x; Bs[lcol + 1][lrow] = b0.y;
        Bs[lcol + 2][lrow] = b0.z; Bs[lcol + 3][lrow] = b0.w;
        Bs[lcol + 0][lrow + 64] = b1.x; Bs[lcol + 1][lrow + 64] = b1.y;
        Bs[lcol + 2][lrow + 64] = b1.z; Bs[lcol + 3][lrow + 64] = b1.w;
        __syncthreads();

#pragma unroll
        for (int kk = 0; kk < 16; kk++) {
            float a[8], b[8];
            *(float4*)(a)     = *(const float4*)(&As[kk][tr * 8]);
            *(float4*)(a + 4) = *(const float4*)(&As[kk][tr * 8 + 4]);
            *(float4*)(b)     = *(const float4*)(&Bs[kk][tc * 8]);
            *(float4*)(b + 4) = *(const float4*)(&Bs[kk][tc * 8 + 4]);
#pragma unroll
            for (int i = 0; i < 8; i++)
#pragma unroll
                for (int j = 0; j < 8; j++)
                    acc[i][j] = fmaf(a[i], b[j], acc[i][j]);
        }
        __syncthreads();
    }

#pragma unroll
    for (int i = 0; i < 8; i++) {
        int row = bm + tr * 8 + i;
#pragma unroll
        for (int j = 0; j < 8; j++) {
            int col = bn + tc * 8 + j;
            if (mode == 0) {
                C[(size_t)row * N + col] = acc[i][j];
            } else {
                int h = col >> 7, d = col & 127;
                C[((size_t)h * M + row) * HD + d] = acc[i][j];
            }
        }
    }
}

// ---------------------------------------------------------------------------
// RoPE, applied in place to g_Q (32 heads) then g_K (8 heads).
// angle computed in double to stay within ~1e-7 of reference fp32 trig.
// ---------------------------------------------------------------------------
__global__ __launch_bounds__(256) void rope_kernel(float* __restrict__ Q,
                                                   float* __restrict__ Kc,
                                                   const int* __restrict__ pos)
{
    int idx = blockIdx.x * blockDim.x + threadIdx.x;   // (h, s, d) packed
    int d = idx & 63;
    int s = (idx >> 6) & (SEQ - 1);
    int h = idx >> 18;

    float* base = (h < NHEADS)
        ? (Q  + ((size_t)h * SEQ + s) * HD)
        : (Kc + ((size_t)(h - NHEADS) * SEQ + s) * HD);

    // inv_freq = 10000^{-d/64}
    double ang = (double)pos[s] * exp(-(double)d * (9.210340371976184 / 64.0));
    float c  = (float)cos(ang);
    float si = (float)sin(ang);
    float x1 = base[d], x2 = base[d + 64];
    base[d]      = x1 * c - x2 * si;
    base[d + 64] = x2 * c + x1 * si;
}

// ---------------------------------------------------------------------------
// Flash attention, fp32. Grid (SEQ/64, NHEADS), 256 threads.
// smem: Qs[64][128] | Kt[128][65] (transposed K) | Vs[64][128] | Ps[64][64]
// Per thread: 4x4 micro-tile of S, 4x8 micro-tile of O. 16-lane shuffle
// row reductions (rows split across the 16 threads sharing tid>>4).
// ---------------------------------------------------------------------------
__global__ __launch_bounds__(256) void flash_attn(const float* __restrict__ Q,
                                                  const float* __restrict__ K,
                                                  const float* __restrict__ V,
                                                  float* __restrict__ Out)
{
    extern __shared__ float sm[];
    float* Qs = sm;                        // 8192 floats
    float* Kt = Qs + 64 * 128;             // 128*65 = 8320
    float* Vs = Kt + 128 * 65;             // 8192
    float* Ps = Vs + 64 * 128;             // 4096

    const int tid = threadIdx.x;
    const int qb  = blockIdx.x;
    const int h   = blockIdx.y;

    const float* Qg = Q + ((size_t)h * SEQ + (size_t)qb * 64) * HD;
    const float* Kg = K + (size_t)(h >> 2) * SEQ * HD;
    const float* Vg = V + (size_t)(h >> 2) * SEQ * HD;

    for (int f = tid; f < 2048; f += 256)
        ((float4*)Qs)[f] = ((const float4*)Qg)[f];

    const int tr = tid >> 4, tc = tid & 15;
    const int r0 = tr * 4;      // S/O rows
    const int cs = tc * 4;      // S cols
    const int co = tc * 8;      // O cols

    float m_[4], l_[4], O[4][8];
#pragma unroll
    for (int i = 0; i < 4; i++) {
        m_[i] = -INFINITY; l_[i] = 0.f;
#pragma unroll
        for (int j = 0; j < 8; j++) O[i][j] = 0.f;
    }

    const float scale = 0.08838834764831845f;   // 1/sqrt(128)

    for (int kb = 0; kb <= qb; kb++) {
        __syncthreads();   // protect Kt/Vs rewrite (and Q load on iter 0)
        const float* Kgb = Kg + (size_t)kb * 64 * HD;
        const float* Vgb = Vg + (size_t)kb * 64 * HD;
        for (int f = tid; f < 2048; f += 256) {
            int kr = f >> 5;
            int d0 = (f & 31) << 2;
            float4 kv = ((const float4*)Kgb)[f];
            Kt[(d0 + 0) * 65 + kr] = kv.x;
            Kt[(d0 + 1) * 65 + kr] = kv.y;
            Kt[(d0 + 2) * 65 + kr] = kv.z;
            Kt[(d0 + 3) * 65 + kr] = kv.w;
            ((float4*)Vs)[f] = ((const float4*)Vgb)[f];
        }
        __syncthreads();

        // S = Qs @ Kt  (4x4 per thread)
        float s4[4][4];
#pragma unroll
        for (int i = 0; i < 4; i++)
#pragma unroll
            for (int j = 0; j < 4; j++) s4[i][j] = 0.f;

#pragma unroll 4
        for (int d = 0; d < 128; d++) {
            float q0 = Qs[(r0 + 0) * 128 + d];
            float q1 = Qs[(r0 + 1) * 128 + d];
            float q2 = Qs[(r0 + 2) * 128 + d];
            float q3 = Qs[(r0 + 3) * 128 + d];
            float k0 = Kt[d * 65 + cs + 0];
            float k1 = Kt[d * 65 + cs + 1];
            float k2 = Kt[d * 65 + cs + 2];
            float k3 = Kt[d * 65 + cs + 3];
            s4[0][0] = fmaf(q0, k0, s4[0][0]); s4[0][1] = fmaf(q0, k1, s4[0][1]);
            s4[0][2] = fmaf(q0, k2, s4[0][2]); s4[0][3] = fmaf(q0, k3, s4[0][3]);
            s4[1][0] = fmaf(q1, k0, s4[1][0]); s4[1][1] = fmaf(q1, k1, s4[1][1]);
            s4[1][2] = fmaf(q1, k2, s4[1][2]); s4[1][3] = fmaf(q1, k3, s4[1][3]);
            s4[2][0] = fmaf(q2, k0, s4[2][0]); s4[2][1] = fmaf(q2, k1, s4[2][1]);
            s4[2][2] = fmaf(q2, k2, s4[2][2]); s4[2][3] = fmaf(q2, k3, s4[2][3]);
            s4[3][0] = fmaf(q3, k0, s4[3][0]); s4[3][1] = fmaf(q3, k1, s4[3][1]);
            s4[3][2] = fmaf(q3, k2, s4[3][2]); s4[3][3] = fmaf(q3, k3, s4[3][3]);
        }

        const bool diag = (kb == qb);
#pragma unroll
        for (int i = 0; i < 4; i++) {
            float tm = -INFINITY;
#pragma unroll
            for (int j = 0; j < 4; j++) {
                float v = s4[i][j] * scale;
                if (diag && (cs + j > r0 + i)) v = -INFINITY;
                s4[i][j] = v;
                tm = fmaxf(tm, v);
            }
#pragma unroll
            for (int off = 1; off < 16; off <<= 1)
                tm = fmaxf(tm, __shfl_xor_sync(0xffffffffu, tm, off));
            float mn = fmaxf(m_[i], tm);
            float al = expf(m_[i] - mn);    // expf(-inf)=0 on first tile
            float rs = 0.f;
#pragma unroll
            for (int j = 0; j < 4; j++) {
                float p = expf(s4[i][j] - mn);
                s4[i][j] = p;
                rs += p;
            }
#pragma unroll
            for (int off = 1; off < 16; off <<= 1)
                rs += __shfl_xor_sync(0xffffffffu, rs, off);
            l_[i] = l_[i] * al + rs;
            m_[i] = mn;
#pragma unroll
            for (int j = 0; j < 8; j++) O[i][j] *= al;
            *(float4*)(Ps + (r0 + i) * 64 + cs) =
                make_float4(s4[i][0], s4[i][1], s4[i][2], s4[i][3]);
        }
        __syncthreads();

        // O += P @ V  (4x8 per thread)
#pragma unroll 2
        for (int k = 0; k < 64; k++) {
            float4 v0 = *(const float4*)(Vs + k * 128 + co);
            float4 v1 = *(const float4*)(Vs + k * 128 + co + 4);
#pragma unroll
            for (int i = 0; i < 4; i++) {
                float p = Ps[(r0 + i) * 64 + k];
                O[i][0] = fmaf(p, v0.x, O[i][0]);
                O[i][1] = fmaf(p, v0.y, O[i][1]);
                O[i][2] = fmaf(p, v0.z, O[i][2]);
                O[i][3] = fmaf(p, v0.w, O[i][3]);
                O[i][4] = fmaf(p, v1.x, O[i][4]);
                O[i][5] = fmaf(p, v1.y, O[i][5]);
                O[i][6] = fmaf(p, v1.z, O[i][6]);
                O[i][7] = fmaf(p, v1.w, O[i][7]);
            }
        }
    }

#pragma unroll
    for (int i = 0; i < 4; i++) {
        float inv = 1.f / l_[i];
        size_t row = (size_t)qb * 64 + r0 + i;
        float* op = Out + row * HID + (size_t)h * HD + co;
        *(float4*)op =
            make_float4(O[i][0] * inv, O[i][1] * inv, O[i][2] * inv, O[i][3] * inv);
        *(float4*)(op + 4) =
            make_float4(O[i][4] * inv, O[i][5] * inv, O[i][6] * inv, O[i][7] * inv);
    }
}

// ---------------------------------------------------------------------------
extern "C" void kernel_launch(void* const* d_in, const int* in_sizes, int n_in,
                              void* d_out, int out_size)
{
    const float* Hs = (const float*)d_in[0];
    const float* Wq = (const float*)d_in[1];
    const float* Wk = (const float*)d_in[2];
    const float* Wv = (const float*)d_in[3];
    const float* Wo = (const float*)d_in[4];
    const int*  pos = (const int*)d_in[5];
    float* out = (float*)d_out;

    float *Qp, *Kp, *Vp, *Ap;
    cudaGetSymbolAddress((void**)&Qp, g_Q);
    cudaGetSymbolAddress((void**)&Kp, g_K);
    cudaGetSymbolAddress((void**)&Vp, g_V);
    cudaGetSymbolAddress((void**)&Ap, g_A);

    const int FLASH_SMEM = (64 * 128 + 128 * 65 + 64 * 128 + 64 * 64) * 4; // 115200
    cudaFuncSetAttribute(flash_attn, cudaFuncAttributeMaxDynamicSharedMemorySize,
                         FLASH_SMEM);

    // QKV projections (epilogue scatters into head-major layout)
    sgemm_nt<<<dim3((NHEADS * HD) / 128, SEQ / 128), 256>>>(Hs, Wq, Qp,
                                                            SEQ, NHEADS * HD, HID, 1);
    sgemm_nt<<<dim3((NKV * HD) / 128, SEQ / 128), 256>>>(Hs, Wk, Kp,
                                                         SEQ, NKV * HD, HID, 1);
    sgemm_nt<<<dim3((NKV * HD) / 128, SEQ / 128), 256>>>(Hs, Wv, Vp,
                                                         SEQ, NKV * HD, HID, 1);

    // RoPE on Q and K
    rope_kernel<<<((NHEADS + NKV) * SEQ * 64) / 256, 256>>>(Qp, Kp, pos);

    // Causal flash attention -> g_A [seq][head*128]
    flash_attn<<<dim3(SEQ / 64, NHEADS), 256, FLASH_SMEM>>>(Qp, Kp, Vp, Ap);

    // Output projection -> d_out
    sgemm_nt<<<dim3(HID / 128, SEQ / 128), 256>>>(Ap, Wo, out,
                                                  SEQ, HID, NHEADS * HD, 0);
}

// round 2
// speedup vs baseline: 1.5347x; 1.5347x over previous
#include <cuda_runtime.h>
#include <math.h>

#define SEQ    4096
#define HID    4096
#define NHEADS 32
#define NKV    8
#define HD     128

// Scratch (device globals: allocation-free rule)
__device__ float g_Q[(size_t)NHEADS * SEQ * HD];  // [head][seq][128]
__device__ float g_K[(size_t)NKV    * SEQ * HD];  // [kvhead][seq][128]
__device__ float g_V[(size_t)NKV    * SEQ * HD];
__device__ float g_A[(size_t)SEQ * HID];          // attn out, [seq][head*128]

__device__ __forceinline__ unsigned f2tf32(float x) {
    unsigned r;
    asm("cvt.rna.tf32.f32 %0, %1;" : "=r"(r) : "f"(x));
    return r;
}

// ---------------------------------------------------------------------------
// TF32 tensor-core GEMM: C = A(MxK) * B(NxK)^T, row-major inputs.
// Block tile 128x128x32, 8 warps, warp tile 64x32 (4x4 m16n8k8 mma tiles).
// mode 0: C[row*N+col]
// mode 1: scatter head-major C[((col>>7)*M + row)*128 + (col&127)]
// Smem pad 36 => fragment LDS bank = (4*row + k) % 32, conflict-free.
// ---------------------------------------------------------------------------
__global__ __launch_bounds__(256) void sgemm_tf32(const float* __restrict__ A,
                                                  const float* __restrict__ B,
                                                  float* __restrict__ C,
                                                  int M, int N, int K, int mode)
{
    __shared__ float As[128][36];
    __shared__ float Bs[128][36];

    const int tid  = threadIdx.x;
    const int warp = tid >> 5;
    const int lane = tid & 31;
    const int wm   = warp & 1;        // 0..1  -> 64-row half
    const int wn   = warp >> 1;       // 0..3  -> 32-col slice
    const int g    = lane >> 2;       // 0..7
    const int t4   = lane & 3;        // 0..3
    const int bm   = blockIdx.y * 128;
    const int bn   = blockIdx.x * 128;

    float acc[4][4][4];
#pragma unroll
    for (int mt = 0; mt < 4; mt++)
#pragma unroll
        for (int nt = 0; nt < 4; nt++)
#pragma unroll
            for (int c = 0; c < 4; c++) acc[mt][nt][c] = 0.f;

    const int lrow = tid >> 3;        // 0..31 (row within 128, batch stride 32)
    const int lkc  = (tid & 7) << 2;  // 0,4,...,28

    for (int k0 = 0; k0 < K; k0 += 32) {
        float4 ra[4], rb[4];
#pragma unroll
        for (int i = 0; i < 4; i++) {
            int row = lrow + i * 32;
            ra[i] = *(const float4*)(A + (size_t)(bm + row) * K + k0 + lkc);
            rb[i] = *(const float4*)(B + (size_t)(bn + row) * K + k0 + lkc);
        }
        __syncthreads();   // previous mma reads done
#pragma unroll
        for (int i = 0; i < 4; i++) {
            int row = lrow + i * 32;
            As[row][lkc + 0] = __uint_as_float(f2tf32(ra[i].x));
            As[row][lkc + 1] = __uint_as_float(f2tf32(ra[i].y));
            As[row][lkc + 2] = __uint_as_float(f2tf32(ra[i].z));
            As[row][lkc + 3] = __uint_as_float(f2tf32(ra[i].w));
            Bs[row][lkc + 0] = __uint_as_float(f2tf32(rb[i].x));
            Bs[row][lkc + 1] = __uint_as_float(f2tf32(rb[i].y));
            Bs[row][lkc + 2] = __uint_as_float(f2tf32(rb[i].z));
            Bs[row][lkc + 3] = __uint_as_float(f2tf32(rb[i].w));
        }
        __syncthreads();

#pragma unroll
        for (int ks = 0; ks < 4; ks++) {
            const int kk = ks * 8;
            unsigned af[4][4], bf[4][2];
#pragma unroll
            for (int mt = 0; mt < 4; mt++) {
                int r = wm * 64 + mt * 16;
                af[mt][0] = __float_as_uint(As[r + g][kk + t4]);
                af[mt][1] = __float_as_uint(As[r + g + 8][kk + t4]);
                af[mt][2] = __float_as_uint(As[r + g][kk + t4 + 4]);
                af[mt][3] = __float_as_uint(As[r + g + 8][kk + t4 + 4]);
            }
#pragma unroll
            for (int nt = 0; nt < 4; nt++) {
                int c = wn * 32 + nt * 8;
                bf[nt][0] = __float_as_uint(Bs[c + g][kk + t4]);
                bf[nt][1] = __float_as_uint(Bs[c + g][kk + t4 + 4]);
            }
#pragma unroll
            for (int mt = 0; mt < 4; mt++)
#pragma unroll
                for (int nt = 0; nt < 4; nt++) {
                    asm volatile(
                        "mma.sync.aligned.m16n8k8.row.col.f32.tf32.tf32.f32 "
                        "{%0,%1,%2,%3}, {%4,%5,%6,%7}, {%8,%9}, {%0,%1,%2,%3};"
                        : "+f"(acc[mt][nt][0]), "+f"(acc[mt][nt][1]),
                          "+f"(acc[mt][nt][2]), "+f"(acc[mt][nt][3])
                        : "r"(af[mt][0]), "r"(af[mt][1]),
                          "r"(af[mt][2]), "r"(af[mt][3]),
                          "r"(bf[nt][0]), "r"(bf[nt][1]));
                }
        }
    }

#pragma unroll
    for (int mt = 0; mt < 4; mt++) {
#pragma unroll
        for (int nt = 0; nt < 4; nt++) {
            int row = bm + wm * 64 + mt * 16 + g;
            int col = bn + wn * 32 + nt * 8 + 2 * t4;
            if (mode == 0) {
                *(float2*)(C + (size_t)row * N + col) =
                    make_float2(acc[mt][nt][0], acc[mt][nt][1]);
                *(float2*)(C + (size_t)(row + 8) * N + col) =
                    make_float2(acc[mt][nt][2], acc[mt][nt][3]);
            } else {
                int h = col >> 7, d = col & 127;
                *(float2*)(C + ((size_t)h * M + row) * HD + d) =
                    make_float2(acc[mt][nt][0], acc[mt][nt][1]);
                *(float2*)(C + ((size_t)h * M + row + 8) * HD + d) =
                    make_float2(acc[mt][nt][2], acc[mt][nt][3]);
            }
        }
    }
}

// ---------------------------------------------------------------------------
// RoPE, applied in place to g_Q (32 heads) then g_K (8 heads).
// ---------------------------------------------------------------------------
__global__ __launch_bounds__(256) void rope_kernel(float* __restrict__ Q,
                                                   float* __restrict__ Kc,
                                                   const int* __restrict__ pos)
{
    int idx = blockIdx.x * blockDim.x + threadIdx.x;   // (h, s, d) packed
    int d = idx & 63;
    int s = (idx >> 6) & (SEQ - 1);
    int h = idx >> 18;

    float* base = (h < NHEADS)
        ? (Q  + ((size_t)h * SEQ + s) * HD)
        : (Kc + ((size_t)(h - NHEADS) * SEQ + s) * HD);

    double ang = (double)pos[s] * exp(-(double)d * (9.210340371976184 / 64.0));
    float c  = (float)cos(ang);
    float si = (float)sin(ang);
    float x1 = base[d], x2 = base[d + 64];
    base[d]      = x1 * c - x2 * si;
    base[d + 64] = x2 * c + x1 * si;
}

// ---------------------------------------------------------------------------
// Flash attention, fp32 (unchanged from R1). Grid (SEQ/64, NHEADS), 256 thr.
// ---------------------------------------------------------------------------
__global__ __launch_bounds__(256) void flash_attn(const float* __restrict__ Q,
                                                  const float* __restrict__ K,
                                                  const float* __restrict__ V,
                                                  float* __restrict__ Out)
{
    extern __shared__ float sm[];
    float* Qs = sm;
    float* Kt = Qs + 64 * 128;
    float* Vs = Kt + 128 * 65;
    float* Ps = Vs + 64 * 128;

    const int tid = threadIdx.x;
    const int qb  = blockIdx.x;
    const int h   = blockIdx.y;

    const float* Qg = Q + ((size_t)h * SEQ + (size_t)qb * 64) * HD;
    const float* Kg = K + (size_t)(h >> 2) * SEQ * HD;
    const float* Vg = V + (size_t)(h >> 2) * SEQ * HD;

    for (int f = tid; f < 2048; f += 256)
        ((float4*)Qs)[f] = ((const float4*)Qg)[f];

    const int tr = tid >> 4, tc = tid & 15;
    const int r0 = tr * 4;
    const int cs = tc * 4;
    const int co = tc * 8;

    float m_[4], l_[4], O[4][8];
#pragma unroll
    for (int i = 0; i < 4; i++) {
        m_[i] = -INFINITY; l_[i] = 0.f;
#pragma unroll
        for (int j = 0; j < 8; j++) O[i][j] = 0.f;
    }

    const float scale = 0.08838834764831845f;

    for (int kb = 0; kb <= qb; kb++) {
        __syncthreads();
        const float* Kgb = Kg + (size_t)kb * 64 * HD;
        const float* Vgb = Vg + (size_t)kb * 64 * HD;
        for (int f = tid; f < 2048; f += 256) {
            int kr = f >> 5;
            int d0 = (f & 31) << 2;
            float4 kv = ((const float4*)Kgb)[f];
            Kt[(d0 + 0) * 65 + kr] = kv.x;
            Kt[(d0 + 1) * 65 + kr] = kv.y;
            Kt[(d0 + 2) * 65 + kr] = kv.z;
            Kt[(d0 + 3) * 65 + kr] = kv.w;
            ((float4*)Vs)[f] = ((const float4*)Vgb)[f];
        }
        __syncthreads();

        float s4[4][4];
#pragma unroll
        for (int i = 0; i < 4; i++)
#pragma unroll
            for (int j = 0; j < 4; j++) s4[i][j] = 0.f;

#pragma unroll 4
        for (int d = 0; d < 128; d++) {
            float q0 = Qs[(r0 + 0) * 128 + d];
            float q1 = Qs[(r0 + 1) * 128 + d];
            float q2 = Qs[(r0 + 2) * 128 + d];
            float q3 = Qs[(r0 + 3) * 128 + d];
            float k0 = Kt[d * 65 + cs + 0];
            float k1 = Kt[d * 65 + cs + 1];
            float k2 = Kt[d * 65 + cs + 2];
            float k3 = Kt[d * 65 + cs + 3];
            s4[0][0] = fmaf(q0, k0, s4[0][0]); s4[0][1] = fmaf(q0, k1, s4[0][1]);
            s4[0][2] = fmaf(q0, k2, s4[0][2]); s4[0][3] = fmaf(q0, k3, s4[0][3]);
            s4[1][0] = fmaf(q1, k0, s4[1][0]); s4[1][1] = fmaf(q1, k1, s4[1][1]);
            s4[1][2] = fmaf(q1, k2, s4[1][2]); s4[1][3] = fmaf(q1, k3, s4[1][3]);
            s4[2][0] = fmaf(q2, k0, s4[2][0]); s4[2][1] = fmaf(q2, k1, s4[2][1]);
            s4[2][2] = fmaf(q2, k2, s4[2][2]); s4[2][3] = fmaf(q2, k3, s4[2][3]);
            s4[3][0] = fmaf(q3, k0, s4[3][0]); s4[3][1] = fmaf(q3, k1, s4[3][1]);
            s4[3][2] = fmaf(q3, k2, s4[3][2]); s4[3][3] = fmaf(q3, k3, s4[3][3]);
        }

        const bool diag = (kb == qb);
#pragma unroll
        for (int i = 0; i < 4; i++) {
            float tm = -INFINITY;
#pragma unroll
            for (int j = 0; j < 4; j++) {
                float v = s4[i][j] * scale;
                if (diag && (cs + j > r0 + i)) v = -INFINITY;
                s4[i][j] = v;
                tm = fmaxf(tm, v);
            }
#pragma unroll
            for (int off = 1; off < 16; off <<= 1)
                tm = fmaxf(tm, __shfl_xor_sync(0xffffffffu, tm, off));
            float mn = fmaxf(m_[i], tm);
            float al = expf(m_[i] - mn);
            float rs = 0.f;
#pragma unroll
            for (int j = 0; j < 4; j++) {
                float p = expf(s4[i][j] - mn);
                s4[i][j] = p;
                rs += p;
            }
#pragma unroll
            for (int off = 1; off < 16; off <<= 1)
                rs += __shfl_xor_sync(0xffffffffu, rs, off);
            l_[i] = l_[i] * al + rs;
            m_[i] = mn;
#pragma unroll
            for (int j = 0; j < 8; j++) O[i][j] *= al;
            *(float4*)(Ps + (r0 + i) * 64 + cs) =
                make_float4(s4[i][0], s4[i][1], s4[i][2], s4[i][3]);
        }
        __syncthreads();

#pragma unroll 2
        for (int k = 0; k < 64; k++) {
            float4 v0 = *(const float4*)(Vs + k * 128 + co);
            float4 v1 = *(const float4*)(Vs + k * 128 + co + 4);
#pragma unroll
            for (int i = 0; i < 4; i++) {
                float p = Ps[(r0 + i) * 64 + k];
                O[i][0] = fmaf(p, v0.x, O[i][0]);
                O[i][1] = fmaf(p, v0.y, O[i][1]);
                O[i][2] = fmaf(p, v0.z, O[i][2]);
                O[i][3] = fmaf(p, v0.w, O[i][3]);
                O[i][4] = fmaf(p, v1.x, O[i][4]);
                O[i][5] = fmaf(p, v1.y, O[i][5]);
                O[i][6] = fmaf(p, v1.z, O[i][6]);
                O[i][7] = fmaf(p, v1.w, O[i][7]);
            }
        }
    }

#pragma unroll
    for (int i = 0; i < 4; i++) {
        float inv = 1.f / l_[i];
        size_t row = (size_t)qb * 64 + r0 + i;
        float* op = Out + row * HID + (size_t)h * HD + co;
        *(float4*)op =
            make_float4(O[i][0] * inv, O[i][1] * inv, O[i][2] * inv, O[i][3] * inv);
        *(float4*)(op + 4) =
            make_float4(O[i][4] * inv, O[i][5] * inv, O[i][6] * inv, O[i][7] * inv);
    }
}

// ---------------------------------------------------------------------------
extern "C" void kernel_launch(void* const* d_in, const int* in_sizes, int n_in,
                              void* d_out, int out_size)
{
    const float* Hs = (const float*)d_in[0];
    const float* Wq = (const float*)d_in[1];
    const float* Wk = (const float*)d_in[2];
    const float* Wv = (const float*)d_in[3];
    const float* Wo = (const float*)d_in[4];
    const int*  pos = (const int*)d_in[5];
    float* out = (float*)d_out;

    float *Qp, *Kp, *Vp, *Ap;
    cudaGetSymbolAddress((void**)&Qp, g_Q);
    cudaGetSymbolAddress((void**)&Kp, g_K);
    cudaGetSymbolAddress((void**)&Vp, g_V);
    cudaGetSymbolAddress((void**)&Ap, g_A);

    const int FLASH_SMEM = (64 * 128 + 128 * 65 + 64 * 128 + 64 * 64) * 4; // 115200
    cudaFuncSetAttribute(flash_attn, cudaFuncAttributeMaxDynamicSharedMemorySize,
                         FLASH_SMEM);

    // QKV projections (tf32 tensor cores; epilogue scatters head-major)
    sgemm_tf32<<<dim3((NHEADS * HD) / 128, SEQ / 128), 256>>>(Hs, Wq, Qp,
                                                              SEQ, NHEADS * HD, HID, 1);
    sgemm_tf32<<<dim3((NKV * HD) / 128, SEQ / 128), 256>>>(Hs, Wk, Kp,
                                                           SEQ, NKV * HD, HID, 1);
    sgemm_tf32<<<dim3((NKV * HD) / 128, SEQ / 128), 256>>>(Hs, Wv, Vp,
                                                           SEQ, NKV * HD, HID, 1);

    // RoPE on Q and K
    rope_kernel<<<((NHEADS + NKV) * SEQ * 64) / 256, 256>>>(Qp, Kp, pos);

    // Causal flash attention -> g_A [seq][head*128]
    flash_attn<<<dim3(SEQ / 64, NHEADS), 256, FLASH_SMEM>>>(Qp, Kp, Vp, Ap);

    // Output projection -> d_out (tf32 tensor cores)
    sgemm_tf32<<<dim3(HID / 128, SEQ / 128), 256>>>(Ap, Wo, out,
                                                    SEQ, HID, NHEADS * HD, 0);
}

// round 3
// speedup vs baseline: 2.5933x; 1.6898x over previous
#include <cuda_runtime.h>
#include <cuda_bf16.h>
#include <math.h>
#include <stdint.h>

#define SEQ    4096
#define HID    4096
#define NHEADS 32
#define NKV    8
#define HD     128

// Scratch (device globals: allocation-free rule)
__device__ float g_Q[(size_t)NHEADS * SEQ * HD];  // [head][seq][128]
__device__ float g_K[(size_t)NKV    * SEQ * HD];  // [kvhead][seq][128]
__device__ float g_V[(size_t)NKV    * SEQ * HD];
__device__ float g_A[(size_t)SEQ * HID];          // attn out, [seq][head*128]

__device__ __forceinline__ unsigned f2tf32(float x) {
    unsigned r;
    asm("cvt.rna.tf32.f32 %0, %1;" : "=r"(r) : "f"(x));
    return r;
}

// ---------------------------------------------------------------------------
// TF32 tensor-core GEMM (unchanged from R2): C = A(MxK) * B(NxK)^T.
// ---------------------------------------------------------------------------
__global__ __launch_bounds__(256) void sgemm_tf32(const float* __restrict__ A,
                                                  const float* __restrict__ B,
                                                  float* __restrict__ C,
                                                  int M, int N, int K, int mode)
{
    __shared__ float As[128][36];
    __shared__ float Bs[128][36];

    const int tid  = threadIdx.x;
    const int warp = tid >> 5;
    const int lane = tid & 31;
    const int wm   = warp & 1;
    const int wn   = warp >> 1;
    const int g    = lane >> 2;
    const int t4   = lane & 3;
    const int bm   = blockIdx.y * 128;
    const int bn   = blockIdx.x * 128;

    float acc[4][4][4];
#pragma unroll
    for (int mt = 0; mt < 4; mt++)
#pragma unroll
        for (int nt = 0; nt < 4; nt++)
#pragma unroll
            for (int c = 0; c < 4; c++) acc[mt][nt][c] = 0.f;

    const int lrow = tid >> 3;
    const int lkc  = (tid & 7) << 2;

    for (int k0 = 0; k0 < K; k0 += 32) {
        float4 ra[4], rb[4];
#pragma unroll
        for (int i = 0; i < 4; i++) {
            int row = lrow + i * 32;
            ra[i] = *(const float4*)(A + (size_t)(bm + row) * K + k0 + lkc);
            rb[i] = *(const float4*)(B + (size_t)(bn + row) * K + k0 + lkc);
        }
        __syncthreads();
#pragma unroll
        for (int i = 0; i < 4; i++) {
            int row = lrow + i * 32;
            As[row][lkc + 0] = __uint_as_float(f2tf32(ra[i].x));
            As[row][lkc + 1] = __uint_as_float(f2tf32(ra[i].y));
            As[row][lkc + 2] = __uint_as_float(f2tf32(ra[i].z));
            As[row][lkc + 3] = __uint_as_float(f2tf32(ra[i].w));
            Bs[row][lkc + 0] = __uint_as_float(f2tf32(rb[i].x));
            Bs[row][lkc + 1] = __uint_as_float(f2tf32(rb[i].y));
            Bs[row][lkc + 2] = __uint_as_float(f2tf32(rb[i].z));
            Bs[row][lkc + 3] = __uint_as_float(f2tf32(rb[i].w));
        }
        __syncthreads();

#pragma unroll
        for (int ks = 0; ks < 4; ks++) {
            const int kk = ks * 8;
            unsigned af[4][4], bf[4][2];
#pragma unroll
            for (int mt = 0; mt < 4; mt++) {
                int r = wm * 64 + mt * 16;
                af[mt][0] = __float_as_uint(As[r + g][kk + t4]);
                af[mt][1] = __float_as_uint(As[r + g + 8][kk + t4]);
                af[mt][2] = __float_as_uint(As[r + g][kk + t4 + 4]);
                af[mt][3] = __float_as_uint(As[r + g + 8][kk + t4 + 4]);
            }
#pragma unroll
            for (int nt = 0; nt < 4; nt++) {
                int c = wn * 32 + nt * 8;
                bf[nt][0] = __float_as_uint(Bs[c + g][kk + t4]);
                bf[nt][1] = __float_as_uint(Bs[c + g][kk + t4 + 4]);
            }
#pragma unroll
            for (int mt = 0; mt < 4; mt++)
#pragma unroll
                for (int nt = 0; nt < 4; nt++) {
                    asm volatile(
                        "mma.sync.aligned.m16n8k8.row.col.f32.tf32.tf32.f32 "
                        "{%0,%1,%2,%3}, {%4,%5,%6,%7}, {%8,%9}, {%0,%1,%2,%3};"
                        : "+f"(acc[mt][nt][0]), "+f"(acc[mt][nt][1]),
                          "+f"(acc[mt][nt][2]), "+f"(acc[mt][nt][3])
                        : "r"(af[mt][0]), "r"(af[mt][1]),
                          "r"(af[mt][2]), "r"(af[mt][3]),
                          "r"(bf[nt][0]), "r"(bf[nt][1]));
                }
        }
    }

#pragma unroll
    for (int mt = 0; mt < 4; mt++) {
#pragma unroll
        for (int nt = 0; nt < 4; nt++) {
            int row = bm + wm * 64 + mt * 16 + g;
            int col = bn + wn * 32 + nt * 8 + 2 * t4;
            if (mode == 0) {
                *(float2*)(C + (size_t)row * N + col) =
                    make_float2(acc[mt][nt][0], acc[mt][nt][1]);
                *(float2*)(C + (size_t)(row + 8) * N + col) =
                    make_float2(acc[mt][nt][2], acc[mt][nt][3]);
            } else {
                int h = col >> 7, d = col & 127;
                *(float2*)(C + ((size_t)h * M + row) * HD + d) =
                    make_float2(acc[mt][nt][0], acc[mt][nt][1]);
                *(float2*)(C + ((size_t)h * M + row + 8) * HD + d) =
                    make_float2(acc[mt][nt][2], acc[mt][nt][3]);
            }
        }
    }
}

// ---------------------------------------------------------------------------
// RoPE (unchanged)
// ---------------------------------------------------------------------------
__global__ __launch_bounds__(256) void rope_kernel(float* __restrict__ Q,
                                                   float* __restrict__ Kc,
                                                   const int* __restrict__ pos)
{
    int idx = blockIdx.x * blockDim.x + threadIdx.x;
    int d = idx & 63;
    int s = (idx >> 6) & (SEQ - 1);
    int h = idx >> 18;

    float* base = (h < NHEADS)
        ? (Q  + ((size_t)h * SEQ + s) * HD)
        : (Kc + ((size_t)(h - NHEADS) * SEQ + s) * HD);

    double ang = (double)pos[s] * exp(-(double)d * (9.210340371976184 / 64.0));
    float c  = (float)cos(ang);
    float si = (float)sin(ang);
    float x1 = base[d], x2 = base[d + 64];
    base[d]      = x1 * c - x2 * si;
    base[d + 64] = x2 * c + x1 * si;
}

// ---------------------------------------------------------------------------
// bf16x3 tensor-core flash attention.
// CTA: 128 thr (4 warps). q-tile 64, k-tile 64. Warp owns 16 q-rows.
// smem: Qhi/Qlo/Khi/Klo/Vhi/Vlo, each [64][136] bf16 (pad => ldmatrix
// conflict-free). A·B ~= Ahi·Bhi + Ahi·Blo + Alo·Bhi (error ~1.5e-5).
// ---------------------------------------------------------------------------
#define LDB 136

__device__ __forceinline__ void ldsm4(uint32_t a[4], uint32_t addr) {
    asm volatile("ldmatrix.sync.aligned.m8n8.x4.shared.b16 {%0,%1,%2,%3}, [%4];"
        : "=r"(a[0]), "=r"(a[1]), "=r"(a[2]), "=r"(a[3]) : "r"(addr));
}
__device__ __forceinline__ void ldsm2(uint32_t b[2], uint32_t addr) {
    asm volatile("ldmatrix.sync.aligned.m8n8.x2.shared.b16 {%0,%1}, [%2];"
        : "=r"(b[0]), "=r"(b[1]) : "r"(addr));
}
__device__ __forceinline__ void ldsm4t(uint32_t a[4], uint32_t addr) {
    asm volatile("ldmatrix.sync.aligned.m8n8.x4.trans.shared.b16 {%0,%1,%2,%3}, [%4];"
        : "=r"(a[0]), "=r"(a[1]), "=r"(a[2]), "=r"(a[3]) : "r"(addr));
}
__device__ __forceinline__ void mma_bf16(float c[4], const uint32_t a[4],
                                         uint32_t b0, uint32_t b1) {
    asm volatile(
        "mma.sync.aligned.m16n8k16.row.col.f32.bf16.bf16.f32 "
        "{%0,%1,%2,%3}, {%4,%5,%6,%7}, {%8,%9}, {%0,%1,%2,%3};"
        : "+f"(c[0]), "+f"(c[1]), "+f"(c[2]), "+f"(c[3])
        : "r"(a[0]), "r"(a[1]), "r"(a[2]), "r"(a[3]), "r"(b0), "r"(b1));
}
__device__ __forceinline__ uint32_t pack_bf16(float lo, float hi) {
    uint32_t r;
    asm("cvt.rn.bf16x2.f32 %0, %1, %2;" : "=r"(r) : "f"(hi), "f"(lo));
    return r;
}
// split x0,x1 into (hi pair, lo pair) packed bf16x2
__device__ __forceinline__ void split_pack(float x0, float x1,
                                           uint32_t& hi, uint32_t& lo) {
    __nv_bfloat16 h0 = __float2bfloat16(x0), h1 = __float2bfloat16(x1);
    hi = ((uint32_t)__bfloat16_as_ushort(h1) << 16) | __bfloat16_as_ushort(h0);
    lo = pack_bf16(x0 - __bfloat162float(h0), x1 - __bfloat162float(h1));
}
__device__ __forceinline__ void cvt_hl(float x, __nv_bfloat16& h, __nv_bfloat16& l) {
    h = __float2bfloat16(x);
    l = __float2bfloat16(x - __bfloat162float(h));
}

__global__ __launch_bounds__(128, 2) void flash_bf16(const float* __restrict__ Q,
                                                     const float* __restrict__ K,
                                                     const float* __restrict__ V,
                                                     float* __restrict__ Out)
{
    extern __shared__ __align__(16) char smem_raw[];
    const int TILE_B = 64 * LDB * 2;   // 17408 bytes
    __nv_bfloat16* Qhi = (__nv_bfloat16*)(smem_raw);
    __nv_bfloat16* Qlo = (__nv_bfloat16*)(smem_raw + TILE_B);
    __nv_bfloat16* Khi = (__nv_bfloat16*)(smem_raw + 2 * TILE_B);
    __nv_bfloat16* Klo = (__nv_bfloat16*)(smem_raw + 3 * TILE_B);
    __nv_bfloat16* Vhi = (__nv_bfloat16*)(smem_raw + 4 * TILE_B);
    __nv_bfloat16* Vlo = (__nv_bfloat16*)(smem_raw + 5 * TILE_B);

    const uint32_t qhi_s = (uint32_t)__cvta_generic_to_shared(Qhi);
    const uint32_t qlo_s = (uint32_t)__cvta_generic_to_shared(Qlo);
    const uint32_t khi_s = (uint32_t)__cvta_generic_to_shared(Khi);
    const uint32_t klo_s = (uint32_t)__cvta_generic_to_shared(Klo);
    const uint32_t vhi_s = (uint32_t)__cvta_generic_to_shared(Vhi);
    const uint32_t vlo_s = (uint32_t)__cvta_generic_to_shared(Vlo);

    const int tid  = threadIdx.x;
    const int wid  = tid >> 5;
    const int lane = tid & 31;
    const int g    = lane >> 2;
    const int t    = lane & 3;
    const int qb   = gridDim.x - 1 - blockIdx.x;   // big blocks first
    const int h    = blockIdx.y;

    const float* Qg = Q + ((size_t)h * SEQ + (size_t)qb * 64) * HD;
    const float* Kg = K + (size_t)(h >> 2) * SEQ * HD;
    const float* Vg = V + (size_t)(h >> 2) * SEQ * HD;

    // Load + split Q tile
    {
        const float4* Q4 = (const float4*)Qg;
        for (int f = tid; f < 2048; f += 128) {
            int row = f >> 5, d0 = (f & 31) << 2;
            float4 q = Q4[f];
            __nv_bfloat16 h0, l0, h1, l1, h2, l2, h3, l3;
            cvt_hl(q.x, h0, l0); cvt_hl(q.y, h1, l1);
            cvt_hl(q.z, h2, l2); cvt_hl(q.w, h3, l3);
            int o = row * LDB + d0;
            *(__nv_bfloat162*)&Qhi[o]     = __nv_bfloat162(h0, h1);
            *(__nv_bfloat162*)&Qhi[o + 2] = __nv_bfloat162(h2, h3);
            *(__nv_bfloat162*)&Qlo[o]     = __nv_bfloat162(l0, l1);
            *(__nv_bfloat162*)&Qlo[o + 2] = __nv_bfloat162(l2, l3);
        }
    }

    // ldmatrix lane address offsets (element units)
    const int a_row = wid * 16 + (lane & 15);
    const int a_col = (lane >> 4) << 3;                 // 0 or 8
    const int b_row = lane & 7;                         // + 8j
    const int b_col = ((lane >> 3) & 1) << 3;           // + 16ks
    const int v_row = (lane & 7) + (((lane >> 3) & 1) << 3);  // + 16kc
    const int v_col = (lane >> 4) << 3;                 // + 16jp

    float o_[16][4];
    float m0 = -INFINITY, m1 = -INFINITY, l0 = 0.f, l1 = 0.f;
#pragma unroll
    for (int j = 0; j < 16; j++)
#pragma unroll
        for (int c = 0; c < 4; c++) o_[j][c] = 0.f;

    const float scale = 0.08838834764831845f;   // 1/sqrt(128)
    const int rl0 = wid * 16 + g;               // local q-row of c0/c1
    const int rl1 = rl0 + 8;

    for (int kb = 0; kb <= qb; kb++) {
        __syncthreads();   // previous iter's mma reads done (and Q store iter0)
        {
            const float4* K4 = (const float4*)(Kg + (size_t)kb * 64 * HD);
            const float4* V4 = (const float4*)(Vg + (size_t)kb * 64 * HD);
            for (int f = tid; f < 2048; f += 128) {
                int row = f >> 5, d0 = (f & 31) << 2;
                int o = row * LDB + d0;
                float4 kx = K4[f];
                __nv_bfloat16 h0, lo0, h1, lo1, h2, lo2, h3, lo3;
                cvt_hl(kx.x, h0, lo0); cvt_hl(kx.y, h1, lo1);
                cvt_hl(kx.z, h2, lo2); cvt_hl(kx.w, h3, lo3);
                *(__nv_bfloat162*)&Khi[o]     = __nv_bfloat162(h0, h1);
                *(__nv_bfloat162*)&Khi[o + 2] = __nv_bfloat162(h2, h3);
                *(__nv_bfloat162*)&Klo[o]     = __nv_bfloat162(lo0, lo1);
                *(__nv_bfloat162*)&Klo[o + 2] = __nv_bfloat162(lo2, lo3);
                float4 vx = V4[f];
                cvt_hl(vx.x, h0, lo0); cvt_hl(vx.y, h1, lo1);
                cvt_hl(vx.z, h2, lo2); cvt_hl(vx.w, h3, lo3);
                *(__nv_bfloat162*)&Vhi[o]     = __nv_bfloat162(h0, h1);
                *(__nv_bfloat162*)&Vhi[o + 2] = __nv_bfloat162(h2, h3);
                *(__nv_bfloat162*)&Vlo[o]     = __nv_bfloat162(lo0, lo1);
                *(__nv_bfloat162*)&Vlo[o + 2] = __nv_bfloat162(lo2, lo3);
            }
        }
        __syncthreads();

        // ---- S = Q K^T (bf16x3) ----
        float sc[8][4];
#pragma unroll
        for (int j = 0; j < 8; j++)
#pragma unroll
            for (int c = 0; c < 4; c++) sc[j][c] = 0.f;

#pragma unroll
        for (int ks = 0; ks < 8; ks++) {
            uint32_t ahf[4], alf[4];
            uint32_t aoff = ((a_row * LDB) + (ks * 16 + a_col)) * 2;
            ldsm4(ahf, qhi_s + aoff);
            ldsm4(alf, qlo_s + aoff);
#pragma unroll
            for (int j = 0; j < 8; j++) {
                uint32_t bh[2], bl[2];
                uint32_t boff = (((8 * j + b_row) * LDB) + (ks * 16 + b_col)) * 2;
                ldsm2(bh, khi_s + boff);
                ldsm2(bl, klo_s + boff);
                mma_bf16(sc[j], ahf, bh[0], bh[1]);
                mma_bf16(sc[j], ahf, bl[0], bl[1]);
                mma_bf16(sc[j], alf, bh[0], bh[1]);
            }
        }

        // ---- mask + online softmax ----
        const bool diag = (kb == qb);
        float tm0 = -INFINITY, tm1 = -INFINITY;
#pragma unroll
        for (int j = 0; j < 8; j++) {
            float v0 = sc[j][0] * scale, v1 = sc[j][1] * scale;
            float v2 = sc[j][2] * scale, v3 = sc[j][3] * scale;
            if (diag) {
                int c0 = 8 * j + 2 * t;
                if (c0     > rl0) v0 = -INFINITY;
                if (c0 + 1 > rl0) v1 = -INFINITY;
                if (c0     > rl1) v2 = -INFINITY;
                if (c0 + 1 > rl1) v3 = -INFINITY;
            }
            sc[j][0] = v0; sc[j][1] = v1; sc[j][2] = v2; sc[j][3] = v3;
            tm0 = fmaxf(tm0, fmaxf(v0, v1));
            tm1 = fmaxf(tm1, fmaxf(v2, v3));
        }
        tm0 = fmaxf(tm0, __shfl_xor_sync(0xffffffffu, tm0, 1));
        tm0 = fmaxf(tm0, __shfl_xor_sync(0xffffffffu, tm0, 2));
        tm1 = fmaxf(tm1, __shfl_xor_sync(0xffffffffu, tm1, 1));
        tm1 = fmaxf(tm1, __shfl_xor_sync(0xffffffffu, tm1, 2));

        float mn0 = fmaxf(m0, tm0), mn1 = fmaxf(m1, tm1);
        float al0 = __expf(m0 - mn0), al1 = __expf(m1 - mn1);
        m0 = mn0; m1 = mn1;

        float rs0 = 0.f, rs1 = 0.f;
#pragma unroll
        for (int j = 0; j < 8; j++) {
            sc[j][0] = __expf(sc[j][0] - mn0);
            sc[j][1] = __expf(sc[j][1] - mn0);
            sc[j][2] = __expf(sc[j][2] - mn1);
            sc[j][3] = __expf(sc[j][3] - mn1);
            rs0 += sc[j][0] + sc[j][1];
            rs1 += sc[j][2] + sc[j][3];
        }
        rs0 += __shfl_xor_sync(0xffffffffu, rs0, 1);
        rs0 += __shfl_xor_sync(0xffffffffu, rs0, 2);
        rs1 += __shfl_xor_sync(0xffffffffu, rs1, 1);
        rs1 += __shfl_xor_sync(0xffffffffu, rs1, 2);
        l0 = l0 * al0 + rs0;
        l1 = l1 * al1 + rs1;

#pragma unroll
        for (int j = 0; j < 16; j++) {
            o_[j][0] *= al0; o_[j][1] *= al0;
            o_[j][2] *= al1; o_[j][3] *= al1;
        }

        // pack P fragments (hi/lo) for PV: kc -> S cols [16kc,16kc+16)
        uint32_t pah[4][4], pal[4][4];
#pragma unroll
        for (int kc = 0; kc < 4; kc++) {
            int j0 = 2 * kc, j1 = j0 + 1;
            split_pack(sc[j0][0], sc[j0][1], pah[kc][0], pal[kc][0]);
            split_pack(sc[j0][2], sc[j0][3], pah[kc][1], pal[kc][1]);
            split_pack(sc[j1][0], sc[j1][1], pah[kc][2], pal[kc][2]);
            split_pack(sc[j1][2], sc[j1][3], pah[kc][3], pal[kc][3]);
        }

        // ---- O += P V (bf16x3) ----
#pragma unroll
        for (int kc = 0; kc < 4; kc++) {
#pragma unroll
            for (int jp = 0; jp < 8; jp++) {
                uint32_t vh[4], vl[4];
                uint32_t voff = (((kc * 16 + v_row) * LDB) + (jp * 16 + v_col)) * 2;
                ldsm4t(vh, vhi_s + voff);
                ldsm4t(vl, vlo_s + voff);
                mma_bf16(o_[2 * jp],     pah[kc], vh[0], vh[1]);
                mma_bf16(o_[2 * jp],     pah[kc], vl[0], vl[1]);
                mma_bf16(o_[2 * jp],     pal[kc], vh[0], vh[1]);
                mma_bf16(o_[2 * jp + 1], pah[kc], vh[2], vh[3]);
                mma_bf16(o_[2 * jp + 1], pah[kc], vl[2], vl[3]);
                mma_bf16(o_[2 * jp + 1], pal[kc], vh[2], vh[3]);
            }
        }
    }

    // ---- write out ----
    float inv0 = 1.f / l0, inv1 = 1.f / l1;
    size_t r0 = (size_t)qb * 64 + wid * 16 + g;
    float* base0 = Out + r0 * HID + (size_t)h * HD;
    float* base1 = base0 + (size_t)8 * HID;
#pragma unroll
    for (int j = 0; j < 16; j++) {
        int col = 8 * j + 2 * t;
        *(float2*)(base0 + col) = make_float2(o_[j][0] * inv0, o_[j][1] * inv0);
        *(float2*)(base1 + col) = make_float2(o_[j][2] * inv1, o_[j][3] * inv1);
    }
}

// ---------------------------------------------------------------------------
extern "C" void kernel_launch(void* const* d_in, const int* in_sizes, int n_in,
                              void* d_out, int out_size)
{
    const float* Hs = (const float*)d_in[0];
    const float* Wq = (const float*)d_in[1];
    const float* Wk = (const float*)d_in[2];
    const float* Wv = (const float*)d_in[3];
    const float* Wo = (const float*)d_in[4];
    const int*  pos = (const int*)d_in[5];
    float* out = (float*)d_out;

    float *Qp, *Kp, *Vp, *Ap;
    cudaGetSymbolAddress((void**)&Qp, g_Q);
    cudaGetSymbolAddress((void**)&Kp, g_K);
    cudaGetSymbolAddress((void**)&Vp, g_V);
    cudaGetSymbolAddress((void**)&Ap, g_A);

    const int FLASH_SMEM = 6 * 64 * LDB * 2;   // 104448 bytes
    cudaFuncSetAttribute(flash_bf16, cudaFuncAttributeMaxDynamicSharedMemorySize,
                         FLASH_SMEM);

    // QKV projections (tf32 tensor cores; epilogue scatters head-major)
    sgemm_tf32<<<dim3((NHEADS * HD) / 128, SEQ / 128), 256>>>(Hs, Wq, Qp,
                                                              SEQ, NHEADS * HD, HID, 1);
    sgemm_tf32<<<dim3((NKV * HD) / 128, SEQ / 128), 256>>>(Hs, Wk, Kp,
                                                           SEQ, NKV * HD, HID, 1);
    sgemm_tf32<<<dim3((NKV * HD) / 128, SEQ / 128), 256>>>(Hs, Wv, Vp,
                                                           SEQ, NKV * HD, HID, 1);

    // RoPE on Q and K
    rope_kernel<<<((NHEADS + NKV) * SEQ * 64) / 256, 256>>>(Qp, Kp, pos);

    // Causal flash attention (bf16x3 tensor cores) -> g_A [seq][head*128]
    flash_bf16<<<dim3(SEQ / 64, NHEADS), 128, FLASH_SMEM>>>(Qp, Kp, Vp, Ap);

    // Output projection -> d_out (tf32 tensor cores)
    sgemm_tf32<<<dim3(HID / 128, SEQ / 128), 256>>>(Ap, Wo, out,
                                                    SEQ, HID, NHEADS * HD, 0);
}

// round 5
// speedup vs baseline: 2.7786x; 1.0714x over previous
#include <cuda_runtime.h>
#include <cuda_bf16.h>
#include <math.h>
#include <stdint.h>

#define SEQ    4096
#define HID    4096
#define NHEADS 32
#define NKV    8
#define HD     128

// ---------------- device scratch (allocation-free rule) ----------------
__device__ float g_Q[(size_t)NHEADS * SEQ * HD];  // [head][seq][128]
__device__ float g_K[(size_t)NKV    * SEQ * HD];
__device__ float g_V[(size_t)NKV    * SEQ * HD];
__device__ float g_A[(size_t)SEQ * HID];          // flash out (tf32-rounded)
__device__ float g_rH[(size_t)SEQ * HID];         // tf32-rounded operands
__device__ float g_rWq[(size_t)HID * HID];
__device__ float g_rWk[(size_t)NKV * HD * HID];
__device__ float g_rWv[(size_t)NKV * HD * HID];
__device__ float g_rWo[(size_t)HID * HID];

__device__ __forceinline__ unsigned f2tf32(float x) {
    unsigned r;
    asm("cvt.rna.tf32.f32 %0, %1;" : "=r"(r) : "f"(x));
    return r;
}
__device__ __forceinline__ void cp16(uint32_t dst, const void* src) {
    asm volatile("cp.async.cg.shared.global [%0], [%1], 16;"
                 :: "r"(dst), "l"(src) : "memory");
}
__device__ __forceinline__ void cp_commit() {
    asm volatile("cp.async.commit_group;" ::: "memory");
}

// ---------------------------------------------------------------------------
// Pre-round fp32 -> tf32 (rna) elementwise; GEMM then consumes raw bits.
// ---------------------------------------------------------------------------
__global__ __launch_bounds__(256) void round_tf32(const float4* __restrict__ in,
                                                  float4* __restrict__ out, int n4)
{
    int i = blockIdx.x * blockDim.x + threadIdx.x;
    if (i >= n4) return;
    float4 v = in[i];
    v.x = __uint_as_float(f2tf32(v.x));
    v.y = __uint_as_float(f2tf32(v.y));
    v.z = __uint_as_float(f2tf32(v.z));
    v.w = __uint_as_float(f2tf32(v.w));
    out[i] = v;
}

// ---------------------------------------------------------------------------
// TF32 GEMM v2: C = A(MxK) * B(NxK)^T, operands pre-rounded to tf32.
// CTA 128x256, K-tile 32, cp.async double-buffered. 8 warps, warp tile 64x64.
// mode 0: C[row*N+col] ; mode 1: head scatter C[((col>>7)*M+row)*128+(col&127)]
// ---------------------------------------------------------------------------
#define GS_A   (128 * 36)                 // floats per A stage
#define GS_B   (256 * 36)
#define GS_ST  (GS_A + GS_B)              // 13824 floats = 55296 B
#define G_SMEM (2 * GS_ST * 4)            // 110592 B

__device__ __forceinline__ void g_fill(uint32_t smb, int buf,
    const float* __restrict__ A, const float* __restrict__ B,
    int bm, int bn, int K, int kt, int tid)
{
    const uint32_t sa = smb + buf * (GS_ST * 4);
    const uint32_t sb = sa + GS_A * 4;
    const size_t kof = (size_t)kt << 5;
    for (int i = tid; i < 1024; i += 256) {          // A: 128 rows x 8 chunks
        int row = i >> 3, ch = (i & 7) << 4;
        cp16(sa + row * 144 + ch,
             (const char*)(A + (size_t)(bm + row) * K + kof) + ch);
    }
    for (int i = tid; i < 2048; i += 256) {          // B: 256 rows x 8 chunks
        int row = i >> 3, ch = (i & 7) << 4;
        cp16(sb + row * 144 + ch,
             (const char*)(B + (size_t)(bn + row) * K + kof) + ch);
    }
    cp_commit();
}

__global__ __launch_bounds__(256, 1) void gemm_tf32_v2(
    const float* __restrict__ A, const float* __restrict__ B,
    float* __restrict__ C, int M, int N, int K, int mode)
{
    extern __shared__ __align__(16) float sm[];
    const uint32_t smb = (uint32_t)__cvta_generic_to_shared(sm);

    const int tid  = threadIdx.x;
    const int warp = tid >> 5;
    const int lane = tid & 31;
    const int wm   = warp & 1;        // 2 -> 64-row half
    const int wn   = warp >> 1;       // 4 -> 64-col slice
    const int g    = lane >> 2;
    const int t4   = lane & 3;
    const int bm   = blockIdx.y * 128;
    const int bn   = blockIdx.x * 256;

    float acc[4][8][4];
#pragma unroll
    for (int mt = 0; mt < 4; mt++)
#pragma unroll
        for (int nt = 0; nt < 8; nt++)
#pragma unroll
            for (int c = 0; c < 4; c++) acc[mt][nt][c] = 0.f;

    const int KT = K >> 5;
    g_fill(smb, 0, A, B, bm, bn, K, 0, tid);

    for (int kt = 0; kt < KT; kt++) {
        const int buf = kt & 1;
        if (kt + 1 < KT) {
            g_fill(smb, buf ^ 1, A, B, bm, bn, K, kt + 1, tid);
            asm volatile("cp.async.wait_group 1;" ::: "memory");
        } else {
            asm volatile("cp.async.wait_group 0;" ::: "memory");
        }
        __syncthreads();

        const float* As = sm + buf * GS_ST;
        const float* Bs = As + GS_A;

#pragma unroll
        for (int ks = 0; ks < 4; ks++) {
            const int kk = ks * 8;
            unsigned af[4][4], bf[8][2];
#pragma unroll
            for (int mt = 0; mt < 4; mt++) {
                int r = wm * 64 + mt * 16;
                af[mt][0] = __float_as_uint(As[(r + g)     * 36 + kk + t4]);
                af[mt][1] = __float_as_uint(As[(r + g + 8) * 36 + kk + t4]);
                af[mt][2] = __float_as_uint(As[(r + g)     * 36 + kk + t4 + 4]);
                af[mt][3] = __float_as_uint(As[(r + g + 8) * 36 + kk + t4 + 4]);
            }
#pragma unroll
            for (int nt = 0; nt < 8; nt++) {
                int c = wn * 64 + nt * 8;
                bf[nt][0] = __float_as_uint(Bs[(c + g) * 36 + kk + t4]);
                bf[nt][1] = __float_as_uint(Bs[(c + g) * 36 + kk + t4 + 4]);
            }
#pragma unroll
            for (int mt = 0; mt < 4; mt++)
#pragma unroll
                for (int nt = 0; nt < 8; nt++) {
                    asm volatile(
                        "mma.sync.aligned.m16n8k8.row.col.f32.tf32.tf32.f32 "
                        "{%0,%1,%2,%3}, {%4,%5,%6,%7}, {%8,%9}, {%0,%1,%2,%3};"
                        : "+f"(acc[mt][nt][0]), "+f"(acc[mt][nt][1]),
                          "+f"(acc[mt][nt][2]), "+f"(acc[mt][nt][3])
                        : "r"(af[mt][0]), "r"(af[mt][1]),
                          "r"(af[mt][2]), "r"(af[mt][3]),
                          "r"(bf[nt][0]), "r"(bf[nt][1]));
                }
        }
        __syncthreads();
    }

#pragma unroll
    for (int mt = 0; mt < 4; mt++) {
#pragma unroll
        for (int nt = 0; nt < 8; nt++) {
            int row = bm + wm * 64 + mt * 16 + g;
            int col = bn + wn * 64 + nt * 8 + 2 * t4;
            if (mode == 0) {
                *(float2*)(C + (size_t)row * N + col) =
                    make_float2(acc[mt][nt][0], acc[mt][nt][1]);
                *(float2*)(C + (size_t)(row + 8) * N + col) =
                    make_float2(acc[mt][nt][2], acc[mt][nt][3]);
            } else {
                int h = col >> 7, d = col & 127;
                *(float2*)(C + ((size_t)h * M + row) * HD + d) =
                    make_float2(acc[mt][nt][0], acc[mt][nt][1]);
                *(float2*)(C + ((size_t)h * M + row + 8) * HD + d) =
                    make_float2(acc[mt][nt][2], acc[mt][nt][3]);
            }
        }
    }
}

// ---------------------------------------------------------------------------
// RoPE (unchanged)
// ---------------------------------------------------------------------------
__global__ __launch_bounds__(256) void rope_kernel(float* __restrict__ Q,
                                                   float* __restrict__ Kc,
                                                   const int* __restrict__ pos)
{
    int idx = blockIdx.x * blockDim.x + threadIdx.x;
    int d = idx & 63;
    int s = (idx >> 6) & (SEQ - 1);
    int h = idx >> 18;

    float* base = (h < NHEADS)
        ? (Q  + ((size_t)h * SEQ + s) * HD)
        : (Kc + ((size_t)(h - NHEADS) * SEQ + s) * HD);

    double ang = (double)pos[s] * exp(-(double)d * (9.210340371976184 / 64.0));
    float c  = (float)cos(ang);
    float si = (float)sin(ang);
    float x1 = base[d], x2 = base[d + 64];
    base[d]      = x1 * c - x2 * si;
    base[d + 64] = x2 * c + x1 * si;
}

// ---------------------------------------------------------------------------
// bf16x3 flash attention (R3), epilogue tf32-rounds output for O-proj.
// ---------------------------------------------------------------------------
#define LDB 136

__device__ __forceinline__ void ldsm4(uint32_t a[4], uint32_t addr) {
    asm volatile("ldmatrix.sync.aligned.m8n8.x4.shared.b16 {%0,%1,%2,%3}, [%4];"
        : "=r"(a[0]), "=r"(a[1]), "=r"(a[2]), "=r"(a[3]) : "r"(addr));
}
__device__ __forceinline__ void ldsm2(uint32_t b[2], uint32_t addr) {
    asm volatile("ldmatrix.sync.aligned.m8n8.x2.shared.b16 {%0,%1}, [%2];"
        : "=r"(b[0]), "=r"(b[1]) : "r"(addr));
}
__device__ __forceinline__ void ldsm4t(uint32_t a[4], uint32_t addr) {
    asm volatile("ldmatrix.sync.aligned.m8n8.x4.trans.shared.b16 {%0,%1,%2,%3}, [%4];"
        : "=r"(a[0]), "=r"(a[1]), "=r"(a[2]), "=r"(a[3]) : "r"(addr));
}
__device__ __forceinline__ void mma_bf16(float c[4], const uint32_t a[4],
                                         uint32_t b0, uint32_t b1) {
    asm volatile(
        "mma.sync.aligned.m16n8k16.row.col.f32.bf16.bf16.f32 "
        "{%0,%1,%2,%3}, {%4,%5,%6,%7}, {%8,%9}, {%0,%1,%2,%3};"
        : "+f"(c[0]), "+f"(c[1]), "+f"(c[2]), "+f"(c[3])
        : "r"(a[0]), "r"(a[1]), "r"(a[2]), "r"(a[3]), "r"(b0), "r"(b1));
}
__device__ __forceinline__ uint32_t pack_bf16(float lo, float hi) {
    uint32_t r;
    asm("cvt.rn.bf16x2.f32 %0, %1, %2;" : "=r"(r) : "f"(hi), "f"(lo));
    return r;
}
__device__ __forceinline__ void split_pack(float x0, float x1,
                                           uint32_t& hi, uint32_t& lo) {
    __nv_bfloat16 h0 = __float2bfloat16(x0), h1 = __float2bfloat16(x1);
    hi = ((uint32_t)__bfloat16_as_ushort(h1) << 16) | __bfloat16_as_ushort(h0);
    lo = pack_bf16(x0 - __bfloat162float(h0), x1 - __bfloat162float(h1));
}
__device__ __forceinline__ void cvt_hl(float x, __nv_bfloat16& h, __nv_bfloat16& l) {
    h = __float2bfloat16(x);
    l = __float2bfloat16(x - __bfloat162float(h));
}

__global__ __launch_bounds__(128, 2) void flash_bf16(const float* __restrict__ Q,
                                                     const float* __restrict__ K,
                                                     const float* __restrict__ V,
                                                     float* __restrict__ Out)
{
    extern __shared__ __align__(16) char smem_raw[];
    const int TILE_B = 64 * LDB * 2;
    __nv_bfloat16* Qhi = (__nv_bfloat16*)(smem_raw);
    __nv_bfloat16* Qlo = (__nv_bfloat16*)(smem_raw + TILE_B);
    __nv_bfloat16* Khi = (__nv_bfloat16*)(smem_raw + 2 * TILE_B);
    __nv_bfloat16* Klo = (__nv_bfloat16*)(smem_raw + 3 * TILE_B);
    __nv_bfloat16* Vhi = (__nv_bfloat16*)(smem_raw + 4 * TILE_B);
    __nv_bfloat16* Vlo = (__nv_bfloat16*)(smem_raw + 5 * TILE_B);

    const uint32_t qhi_s = (uint32_t)__cvta_generic_to_shared(Qhi);
    const uint32_t qlo_s = (uint32_t)__cvta_generic_to_shared(Qlo);
    const uint32_t khi_s = (uint32_t)__cvta_generic_to_shared(Khi);
    const uint32_t klo_s = (uint32_t)__cvta_generic_to_shared(Klo);
    const uint32_t vhi_s = (uint32_t)__cvta_generic_to_shared(Vhi);
    const uint32_t vlo_s = (uint32_t)__cvta_generic_to_shared(Vlo);

    const int tid  = threadIdx.x;
    const int wid  = tid >> 5;
    const int lane = tid & 31;
    const int g    = lane >> 2;
    const int t    = lane & 3;
    const int qb   = gridDim.x - 1 - blockIdx.x;
    const int h    = blockIdx.y;

    const float* Qg = Q + ((size_t)h * SEQ + (size_t)qb * 64) * HD;
    const float* Kg = K + (size_t)(h >> 2) * SEQ * HD;
    const float* Vg = V + (size_t)(h >> 2) * SEQ * HD;

    {
        const float4* Q4 = (const float4*)Qg;
        for (int f = tid; f < 2048; f += 128) {
            int row = f >> 5, d0 = (f & 31) << 2;
            float4 q = Q4[f];
            __nv_bfloat16 h0, l0, h1, l1, h2, l2, h3, l3;
            cvt_hl(q.x, h0, l0); cvt_hl(q.y, h1, l1);
            cvt_hl(q.z, h2, l2); cvt_hl(q.w, h3, l3);
            int o = row * LDB + d0;
            *(__nv_bfloat162*)&Qhi[o]     = __nv_bfloat162(h0, h1);
            *(__nv_bfloat162*)&Qhi[o + 2] = __nv_bfloat162(h2, h3);
            *(__nv_bfloat162*)&Qlo[o]     = __nv_bfloat162(l0, l1);
            *(__nv_bfloat162*)&Qlo[o + 2] = __nv_bfloat162(l2, l3);
        }
    }

    const int a_row = wid * 16 + (lane & 15);
    const int a_col = (lane >> 4) << 3;
    const int b_row = lane & 7;
    const int b_col = ((lane >> 3) & 1) << 3;
    const int v_row = (lane & 7) + (((lane >> 3) & 1) << 3);
    const int v_col = (lane >> 4) << 3;

    float o_[16][4];
    float m0 = -INFINITY, m1 = -INFINITY, l0 = 0.f, l1 = 0.f;
#pragma unroll
    for (int j = 0; j < 16; j++)
#pragma unroll
        for (int c = 0; c < 4; c++) o_[j][c] = 0.f;

    const float scale = 0.08838834764831845f;
    const int rl0 = wid * 16 + g;
    const int rl1 = rl0 + 8;

    for (int kb = 0; kb <= qb; kb++) {
        __syncthreads();
        {
            const float4* K4 = (const float4*)(Kg + (size_t)kb * 64 * HD);
            const float4* V4 = (const float4*)(Vg + (size_t)kb * 64 * HD);
            for (int f = tid; f < 2048; f += 128) {
                int row = f >> 5, d0 = (f & 31) << 2;
                int o = row * LDB + d0;
                float4 kx = K4[f];
                __nv_bfloat16 h0, lo0, h1, lo1, h2, lo2, h3, lo3;
                cvt_hl(kx.x, h0, lo0); cvt_hl(kx.y, h1, lo1);
                cvt_hl(kx.z, h2, lo2); cvt_hl(kx.w, h3, lo3);
                *(__nv_bfloat162*)&Khi[o]     = __nv_bfloat162(h0, h1);
                *(__nv_bfloat162*)&Khi[o + 2] = __nv_bfloat162(h2, h3);
                *(__nv_bfloat162*)&Klo[o]     = __nv_bfloat162(lo0, lo1);
                *(__nv_bfloat162*)&Klo[o + 2] = __nv_bfloat162(lo2, lo3);
                float4 vx = V4[f];
                cvt_hl(vx.x, h0, lo0); cvt_hl(vx.y, h1, lo1);
                cvt_hl(vx.z, h2, lo2); cvt_hl(vx.w, h3, lo3);
                *(__nv_bfloat162*)&Vhi[o]     = __nv_bfloat162(h0, h1);
                *(__nv_bfloat162*)&Vhi[o + 2] = __nv_bfloat162(h2, h3);
                *(__nv_bfloat162*)&Vlo[o]     = __nv_bfloat162(lo0, lo1);
                *(__nv_bfloat162*)&Vlo[o + 2] = __nv_bfloat162(lo2, lo3);
            }
        }
        __syncthreads();

        float sc[8][4];
#pragma unroll
        for (int j = 0; j < 8; j++)
#pragma unroll
            for (int c = 0; c < 4; c++) sc[j][c] = 0.f;

#pragma unroll
        for (int ks = 0; ks < 8; ks++) {
            uint32_t ahf[4], alf[4];
            uint32_t aoff = ((a_row * LDB) + (ks * 16 + a_col)) * 2;
            ldsm4(ahf, qhi_s + aoff);
            ldsm4(alf, qlo_s + aoff);
#pragma unroll
            for (int j = 0; j < 8; j++) {
                uint32_t bh[2], bl[2];
                uint32_t boff = (((8 * j + b_row) * LDB) + (ks * 16 + b_col)) * 2;
                ldsm2(bh, khi_s + boff);
                ldsm2(bl, klo_s + boff);
                mma_bf16(sc[j], ahf, bh[0], bh[1]);
                mma_bf16(sc[j], ahf, bl[0], bl[1]);
                mma_bf16(sc[j], alf, bh[0], bh[1]);
            }
        }

        const bool diag = (kb == qb);
        float tm0 = -INFINITY, tm1 = -INFINITY;
#pragma unroll
        for (int j = 0; j < 8; j++) {
            float v0 = sc[j][0] * scale, v1 = sc[j][1] * scale;
            float v2 = sc[j][2] * scale, v3 = sc[j][3] * scale;
            if (diag) {
                int c0 = 8 * j + 2 * t;
                if (c0     > rl0) v0 = -INFINITY;
                if (c0 + 1 > rl0) v1 = -INFINITY;
                if (c0     > rl1) v2 = -INFINITY;
                if (c0 + 1 > rl1) v3 = -INFINITY;
            }
            sc[j][0] = v0; sc[j][1] = v1; sc[j][2] = v2; sc[j][3] = v3;
            tm0 = fmaxf(tm0, fmaxf(v0, v1));
            tm1 = fmaxf(tm1, fmaxf(v2, v3));
        }
        tm0 = fmaxf(tm0, __shfl_xor_sync(0xffffffffu, tm0, 1));
        tm0 = fmaxf(tm0, __shfl_xor_sync(0xffffffffu, tm0, 2));
        tm1 = fmaxf(tm1, __shfl_xor_sync(0xffffffffu, tm1, 1));
        tm1 = fmaxf(tm1, __shfl_xor_sync(0xffffffffu, tm1, 2));

        float mn0 = fmaxf(m0, tm0), mn1 = fmaxf(m1, tm1);
        float al0 = __expf(m0 - mn0), al1 = __expf(m1 - mn1);
        m0 = mn0; m1 = mn1;

        float rs0 = 0.f, rs1 = 0.f;
#pragma unroll
        for (int j = 0; j < 8; j++) {
            sc[j][0] = __expf(sc[j][0] - mn0);
            sc[j][1] = __expf(sc[j][1] - mn0);
            sc[j][2] = __expf(sc[j][2] - mn1);
            sc[j][3] = __expf(sc[j][3] - mn1);
            rs0 += sc[j][0] + sc[j][1];
            rs1 += sc[j][2] + sc[j][3];
        }
        rs0 += __shfl_xor_sync(0xffffffffu, rs0, 1);
        rs0 += __shfl_xor_sync(0xffffffffu, rs0, 2);
        rs1 += __shfl_xor_sync(0xffffffffu, rs1, 1);
        rs1 += __shfl_xor_sync(0xffffffffu, rs1, 2);
        l0 = l0 * al0 + rs0;
        l1 = l1 * al1 + rs1;

#pragma unroll
        for (int j = 0; j < 16; j++) {
            o_[j][0] *= al0; o_[j][1] *= al0;
            o_[j][2] *= al1; o_[j][3] *= al1;
        }

        uint32_t pah[4][4], pal[4][4];
#pragma unroll
        for (int kc = 0; kc < 4; kc++) {
            int j0 = 2 * kc, j1 = j0 + 1;
            split_pack(sc[j0][0], sc[j0][1], pah[kc][0], pal[kc][0]);
            split_pack(sc[j0][2], sc[j0][3], pah[kc][1], pal[kc][1]);
            split_pack(sc[j1][0], sc[j1][1], pah[kc][2], pal[kc][2]);
            split_pack(sc[j1][2], sc[j1][3], pah[kc][3], pal[kc][3]);
        }

#pragma unroll
        for (int kc = 0; kc < 4; kc++) {
#pragma unroll
            for (int jp = 0; jp < 8; jp++) {
                uint32_t vh[4], vl[4];
                uint32_t voff = (((kc * 16 + v_row) * LDB) + (jp * 16 + v_col)) * 2;
                ldsm4t(vh, vhi_s + voff);
                ldsm4t(vl, vlo_s + voff);
                mma_bf16(o_[2 * jp],     pah[kc], vh[0], vh[1]);
                mma_bf16(o_[2 * jp],     pah[kc], vl[0], vl[1]);
                mma_bf16(o_[2 * jp],     pal[kc], vh[0], vh[1]);
                mma_bf16(o_[2 * jp + 1], pah[kc], vh[2], vh[3]);
                mma_bf16(o_[2 * jp + 1], pah[kc], vl[2], vl[3]);
                mma_bf16(o_[2 * jp + 1], pal[kc], vh[2], vh[3]);
            }
        }
    }

    // write out, tf32-rounded (O-proj operand pre-rounding)
    float inv0 = 1.f / l0, inv1 = 1.f / l1;
    size_t r0 = (size_t)qb * 64 + wid * 16 + g;
    float* base0 = Out + r0 * HID + (size_t)h * HD;
    float* base1 = base0 + (size_t)8 * HID;
#pragma unroll
    for (int j = 0; j < 16; j++) {
        int col = 8 * j + 2 * t;
        *(float2*)(base0 + col) = make_float2(
            __uint_as_float(f2tf32(o_[j][0] * inv0)),
            __uint_as_float(f2tf32(o_[j][1] * inv0)));
        *(float2*)(base1 + col) = make_float2(
            __uint_as_float(f2tf32(o_[j][2] * inv1)),
            __uint_as_float(f2tf32(o_[j][3] * inv1)));
    }
}

// ---------------------------------------------------------------------------
extern "C" void kernel_launch(void* const* d_in, const int* in_sizes, int n_in,
                              void* d_out, int out_size)
{
    const float* Hs = (const float*)d_in[0];
    const float* Wq = (const float*)d_in[1];
    const float* Wk = (const float*)d_in[2];
    const float* Wv = (const float*)d_in[3];
    const float* Wo = (const float*)d_in[4];
    const int*  pos = (const int*)d_in[5];
    float* out = (float*)d_out;

    float *Qp, *Kp, *Vp, *Ap, *rH, *rWq, *rWk, *rWv, *rWo;
    cudaGetSymbolAddress((void**)&Qp,  g_Q);
    cudaGetSymbolAddress((void**)&Kp,  g_K);
    cudaGetSymbolAddress((void**)&Vp,  g_V);
    cudaGetSymbolAddress((void**)&Ap,  g_A);
    cudaGetSymbolAddress((void**)&rH,  g_rH);
    cudaGetSymbolAddress((void**)&rWq, g_rWq);
    cudaGetSymbolAddress((void**)&rWk, g_rWk);
    cudaGetSymbolAddress((void**)&rWv, g_rWv);
    cudaGetSymbolAddress((void**)&rWo, g_rWo);

    const int FLASH_SMEM = 6 * 64 * LDB * 2;   // 104448
    cudaFuncSetAttribute(flash_bf16, cudaFuncAttributeMaxDynamicSharedMemorySize,
                         FLASH_SMEM);
    cudaFuncSetAttribute(gemm_tf32_v2, cudaFuncAttributeMaxDynamicSharedMemorySize,
                         G_SMEM);

    // tf32 pre-rounding
    const int nH4 = SEQ * HID / 4, nW4 = HID * HID / 4, nKV4 = NKV * HD * HID / 4;
    round_tf32<<<nH4 / 256, 256>>>((const float4*)Hs, (float4*)rH, nH4);
    round_tf32<<<nW4 / 256, 256>>>((const float4*)Wq, (float4*)rWq, nW4);
    round_tf32<<<nKV4 / 256, 256>>>((const float4*)Wk, (float4*)rWk, nKV4);
    round_tf32<<<nKV4 / 256, 256>>>((const float4*)Wv, (float4*)rWv, nKV4);
    round_tf32<<<nW4 / 256, 256>>>((const float4*)Wo, (float4*)rWo, nW4);

    // projections (tf32 v2), head-major scatter
    gemm_tf32_v2<<<dim3(HID / 256, SEQ / 128), 256, G_SMEM>>>(rH, rWq, Qp,
                                                              SEQ, HID, HID, 1);
    gemm_tf32_v2<<<dim3(NKV * HD / 256, SEQ / 128), 256, G_SMEM>>>(rH, rWk, Kp,
                                                                   SEQ, NKV * HD, HID, 1);
    gemm_tf32_v2<<<dim3(NKV * HD / 256, SEQ / 128), 256, G_SMEM>>>(rH, rWv, Vp,
                                                                   SEQ, NKV * HD, HID, 1);

    // RoPE on Q and K
    rope_kernel<<<((NHEADS + NKV) * SEQ * 64) / 256, 256>>>(Qp, Kp, pos);

    // causal flash attention (bf16x3) -> g_A (tf32-rounded)
    flash_bf16<<<dim3(SEQ / 64, NHEADS), 128, FLASH_SMEM>>>(Qp, Kp, Vp, Ap);

    // output projection -> d_out
    gemm_tf32_v2<<<dim3(HID / 256, SEQ / 128), 256, G_SMEM>>>(Ap, rWo, out,
                                                              SEQ, HID, HID, 0);
}

// round 6
// speedup vs baseline: 2.9538x; 1.0631x over previous
#include <cuda_runtime.h>
#include <cuda_bf16.h>
#include <math.h>
#include <stdint.h>

#define SEQ    4096
#define HID    4096
#define NHEADS 32
#define NKV    8
#define HD     128

// ---------------- device scratch (allocation-free rule) ----------------
__device__ float g_Q[(size_t)NHEADS * SEQ * HD];  // [head][seq][128]
__device__ float g_K[(size_t)NKV    * SEQ * HD];
__device__ float g_V[(size_t)NKV    * SEQ * HD];
__device__ float g_A[(size_t)SEQ * HID];          // flash out (tf32-rounded)
__device__ float g_rH[(size_t)SEQ * HID];         // tf32-rounded operands
__device__ float g_rWq[(size_t)HID * HID];
__device__ float g_rWk[(size_t)NKV * HD * HID];
__device__ float g_rWv[(size_t)NKV * HD * HID];
__device__ float g_rWo[(size_t)HID * HID];
__device__ __nv_bfloat16 g_Khi[(size_t)NKV * SEQ * HD];  // split K (post-rope)
__device__ __nv_bfloat16 g_Klo[(size_t)NKV * SEQ * HD];
__device__ __nv_bfloat16 g_Vhi[(size_t)NKV * SEQ * HD];
__device__ __nv_bfloat16 g_Vlo[(size_t)NKV * SEQ * HD];

__device__ __forceinline__ unsigned f2tf32(float x) {
    unsigned r;
    asm("cvt.rna.tf32.f32 %0, %1;" : "=r"(r) : "f"(x));
    return r;
}
__device__ __forceinline__ void cp16(uint32_t dst, const void* src) {
    asm volatile("cp.async.cg.shared.global [%0], [%1], 16;"
                 :: "r"(dst), "l"(src) : "memory");
}
__device__ __forceinline__ void cp_commit() {
    asm volatile("cp.async.commit_group;" ::: "memory");
}
__device__ __forceinline__ void cvt_hl(float x, __nv_bfloat16& h, __nv_bfloat16& l) {
    h = __float2bfloat16(x);
    l = __float2bfloat16(x - __bfloat162float(h));
}

// ---------------------------------------------------------------------------
// Pre-round fp32 -> tf32 (rna)
// ---------------------------------------------------------------------------
__global__ __launch_bounds__(256) void round_tf32(const float4* __restrict__ in,
                                                  float4* __restrict__ out, int n4)
{
    int i = blockIdx.x * blockDim.x + threadIdx.x;
    if (i >= n4) return;
    float4 v = in[i];
    v.x = __uint_as_float(f2tf32(v.x));
    v.y = __uint_as_float(f2tf32(v.y));
    v.z = __uint_as_float(f2tf32(v.z));
    v.w = __uint_as_float(f2tf32(v.w));
    out[i] = v;
}

// ---------------------------------------------------------------------------
// fp32 -> (hi, lo) bf16 split (for V)
// ---------------------------------------------------------------------------
__global__ __launch_bounds__(256) void split_kernel(const float4* __restrict__ in,
                                                    __nv_bfloat162* __restrict__ hi,
                                                    __nv_bfloat162* __restrict__ lo,
                                                    int n4)
{
    int i = blockIdx.x * blockDim.x + threadIdx.x;
    if (i >= n4) return;
    float4 v = in[i];
    __nv_bfloat16 h0, l0, h1, l1, h2, l2, h3, l3;
    cvt_hl(v.x, h0, l0); cvt_hl(v.y, h1, l1);
    cvt_hl(v.z, h2, l2); cvt_hl(v.w, h3, l3);
    hi[2 * i]     = __nv_bfloat162(h0, h1);
    hi[2 * i + 1] = __nv_bfloat162(h2, h3);
    lo[2 * i]     = __nv_bfloat162(l0, l1);
    lo[2 * i + 1] = __nv_bfloat162(l2, l3);
}

// ---------------------------------------------------------------------------
// TF32 GEMM v2 (unchanged from R5)
// ---------------------------------------------------------------------------
#define GS_A   (128 * 36)
#define GS_B   (256 * 36)
#define GS_ST  (GS_A + GS_B)
#define G_SMEM (2 * GS_ST * 4)

__device__ __forceinline__ void g_fill(uint32_t smb, int buf,
    const float* __restrict__ A, const float* __restrict__ B,
    int bm, int bn, int K, int kt, int tid)
{
    const uint32_t sa = smb + buf * (GS_ST * 4);
    const uint32_t sb = sa + GS_A * 4;
    const size_t kof = (size_t)kt << 5;
    for (int i = tid; i < 1024; i += 256) {
        int row = i >> 3, ch = (i & 7) << 4;
        cp16(sa + row * 144 + ch,
             (const char*)(A + (size_t)(bm + row) * K + kof) + ch);
    }
    for (int i = tid; i < 2048; i += 256) {
        int row = i >> 3, ch = (i & 7) << 4;
        cp16(sb + row * 144 + ch,
             (const char*)(B + (size_t)(bn + row) * K + kof) + ch);
    }
    cp_commit();
}

__global__ __launch_bounds__(256, 1) void gemm_tf32_v2(
    const float* __restrict__ A, const float* __restrict__ B,
    float* __restrict__ C, int M, int N, int K, int mode)
{
    extern __shared__ __align__(16) float sm[];
    const uint32_t smb = (uint32_t)__cvta_generic_to_shared(sm);

    const int tid  = threadIdx.x;
    const int warp = tid >> 5;
    const int lane = tid & 31;
    const int wm   = warp & 1;
    const int wn   = warp >> 1;
    const int g    = lane >> 2;
    const int t4   = lane & 3;
    const int bm   = blockIdx.y * 128;
    const int bn   = blockIdx.x * 256;

    float acc[4][8][4];
#pragma unroll
    for (int mt = 0; mt < 4; mt++)
#pragma unroll
        for (int nt = 0; nt < 8; nt++)
#pragma unroll
            for (int c = 0; c < 4; c++) acc[mt][nt][c] = 0.f;

    const int KT = K >> 5;
    g_fill(smb, 0, A, B, bm, bn, K, 0, tid);

    for (int kt = 0; kt < KT; kt++) {
        const int buf = kt & 1;
        if (kt + 1 < KT) {
            g_fill(smb, buf ^ 1, A, B, bm, bn, K, kt + 1, tid);
            asm volatile("cp.async.wait_group 1;" ::: "memory");
        } else {
            asm volatile("cp.async.wait_group 0;" ::: "memory");
        }
        __syncthreads();

        const float* As = sm + buf * GS_ST;
        const float* Bs = As + GS_A;

#pragma unroll
        for (int ks = 0; ks < 4; ks++) {
            const int kk = ks * 8;
            unsigned af[4][4], bf[8][2];
#pragma unroll
            for (int mt = 0; mt < 4; mt++) {
                int r = wm * 64 + mt * 16;
                af[mt][0] = __float_as_uint(As[(r + g)     * 36 + kk + t4]);
                af[mt][1] = __float_as_uint(As[(r + g + 8) * 36 + kk + t4]);
                af[mt][2] = __float_as_uint(As[(r + g)     * 36 + kk + t4 + 4]);
                af[mt][3] = __float_as_uint(As[(r + g + 8) * 36 + kk + t4 + 4]);
            }
#pragma unroll
            for (int nt = 0; nt < 8; nt++) {
                int c = wn * 64 + nt * 8;
                bf[nt][0] = __float_as_uint(Bs[(c + g) * 36 + kk + t4]);
                bf[nt][1] = __float_as_uint(Bs[(c + g) * 36 + kk + t4 + 4]);
            }
#pragma unroll
            for (int mt = 0; mt < 4; mt++)
#pragma unroll
                for (int nt = 0; nt < 8; nt++) {
                    asm volatile(
                        "mma.sync.aligned.m16n8k8.row.col.f32.tf32.tf32.f32 "
                        "{%0,%1,%2,%3}, {%4,%5,%6,%7}, {%8,%9}, {%0,%1,%2,%3};"
                        : "+f"(acc[mt][nt][0]), "+f"(acc[mt][nt][1]),
                          "+f"(acc[mt][nt][2]), "+f"(acc[mt][nt][3])
                        : "r"(af[mt][0]), "r"(af[mt][1]),
                          "r"(af[mt][2]), "r"(af[mt][3]),
                          "r"(bf[nt][0]), "r"(bf[nt][1]));
                }
        }
        __syncthreads();
    }

#pragma unroll
    for (int mt = 0; mt < 4; mt++) {
#pragma unroll
        for (int nt = 0; nt < 8; nt++) {
            int row = bm + wm * 64 + mt * 16 + g;
            int col = bn + wn * 64 + nt * 8 + 2 * t4;
            if (mode == 0) {
                *(float2*)(C + (size_t)row * N + col) =
                    make_float2(acc[mt][nt][0], acc[mt][nt][1]);
                *(float2*)(C + (size_t)(row + 8) * N + col) =
                    make_float2(acc[mt][nt][2], acc[mt][nt][3]);
            } else {
                int h = col >> 7, d = col & 127;
                *(float2*)(C + ((size_t)h * M + row) * HD + d) =
                    make_float2(acc[mt][nt][0], acc[mt][nt][1]);
                *(float2*)(C + ((size_t)h * M + row + 8) * HD + d) =
                    make_float2(acc[mt][nt][2], acc[mt][nt][3]);
            }
        }
    }
}

// ---------------------------------------------------------------------------
// RoPE: Q in place (fp32); K -> split hi/lo bf16 global
// ---------------------------------------------------------------------------
__global__ __launch_bounds__(256) void rope_kernel(float* __restrict__ Q,
                                                   const float* __restrict__ Kc,
                                                   __nv_bfloat16* __restrict__ Khi,
                                                   __nv_bfloat16* __restrict__ Klo,
                                                   const int* __restrict__ pos)
{
    int idx = blockIdx.x * blockDim.x + threadIdx.x;
    int d = idx & 63;
    int s = (idx >> 6) & (SEQ - 1);
    int h = idx >> 18;

    double ang = (double)pos[s] * exp(-(double)d * (9.210340371976184 / 64.0));
    float c  = (float)cos(ang);
    float si = (float)sin(ang);

    if (h < NHEADS) {
        float* base = Q + ((size_t)h * SEQ + s) * HD;
        float x1 = base[d], x2 = base[d + 64];
        base[d]      = x1 * c - x2 * si;
        base[d + 64] = x2 * c + x1 * si;
    } else {
        size_t o = ((size_t)(h - NHEADS) * SEQ + s) * HD;
        float x1 = Kc[o + d], x2 = Kc[o + d + 64];
        float r1 = x1 * c - x2 * si;
        float r2 = x2 * c + x1 * si;
        __nv_bfloat16 hh, ll;
        cvt_hl(r1, hh, ll); Khi[o + d] = hh;       Klo[o + d] = ll;
        cvt_hl(r2, hh, ll); Khi[o + d + 64] = hh;  Klo[o + d + 64] = ll;
    }
}

// ---------------------------------------------------------------------------
// flash v2: q-tile 128, kv-tile 64, 256 thr (8 warps x 16 q-rows),
// cp.async double-buffered pre-split K/V. bf16x3 mma. smem 204 KB, 1 CTA/SM.
// ---------------------------------------------------------------------------
#define LDB 136

__device__ __forceinline__ void ldsm4(uint32_t a[4], uint32_t addr) {
    asm volatile("ldmatrix.sync.aligned.m8n8.x4.shared.b16 {%0,%1,%2,%3}, [%4];"
        : "=r"(a[0]), "=r"(a[1]), "=r"(a[2]), "=r"(a[3]) : "r"(addr));
}
__device__ __forceinline__ void ldsm4t(uint32_t a[4], uint32_t addr) {
    asm volatile("ldmatrix.sync.aligned.m8n8.x4.trans.shared.b16 {%0,%1,%2,%3}, [%4];"
        : "=r"(a[0]), "=r"(a[1]), "=r"(a[2]), "=r"(a[3]) : "r"(addr));
}
__device__ __forceinline__ void mma_bf16(float c[4], const uint32_t a[4],
                                         uint32_t b0, uint32_t b1) {
    asm volatile(
        "mma.sync.aligned.m16n8k16.row.col.f32.bf16.bf16.f32 "
        "{%0,%1,%2,%3}, {%4,%5,%6,%7}, {%8,%9}, {%0,%1,%2,%3};"
        : "+f"(c[0]), "+f"(c[1]), "+f"(c[2]), "+f"(c[3])
        : "r"(a[0]), "r"(a[1]), "r"(a[2]), "r"(a[3]), "r"(b0), "r"(b1));
}
__device__ __forceinline__ uint32_t pack_bf16(float lo, float hi) {
    uint32_t r;
    asm("cvt.rn.bf16x2.f32 %0, %1, %2;" : "=r"(r) : "f"(hi), "f"(lo));
    return r;
}
__device__ __forceinline__ void split_pack(float x0, float x1,
                                           uint32_t& hi, uint32_t& lo) {
    __nv_bfloat16 h0 = __float2bfloat16(x0), h1 = __float2bfloat16(x1);
    hi = ((uint32_t)__bfloat16_as_ushort(h1) << 16) | __bfloat16_as_ushort(h0);
    lo = pack_bf16(x0 - __bfloat162float(h0), x1 - __bfloat162float(h1));
}

#define F_QT_B  (128 * LDB * 2)          // 34816 (one Q tile)
#define F_KT_B  (64 * LDB * 2)           // 17408 (one KV tile)
#define F_STG_B (4 * F_KT_B)             // 69632 (Khi,Klo,Vhi,Vlo)
#define F_SMEM  (2 * F_QT_B + 2 * F_STG_B)   // 208896

__device__ __forceinline__ void f_fill(uint32_t stg,
    const __nv_bfloat16* Khi_g, const __nv_bfloat16* Klo_g,
    const __nv_bfloat16* Vhi_g, const __nv_bfloat16* Vlo_g,
    int kvh, int kb, int tid)
{
    const size_t gof = ((size_t)kvh * SEQ + (size_t)kb * 64) * HD;
    const char* kh = (const char*)(Khi_g + gof);
    const char* kl = (const char*)(Klo_g + gof);
    const char* vh = (const char*)(Vhi_g + gof);
    const char* vl = (const char*)(Vlo_g + gof);
    for (int i = tid; i < 1024; i += 256) {      // 64 rows x 16 chunks(16B)
        int row = i >> 4, ch = (i & 15) << 4;
        uint32_t dst = row * (LDB * 2) + ch;
        int src = row * 256 + ch;
        cp16(stg + dst,               kh + src);
        cp16(stg + F_KT_B + dst,      kl + src);
        cp16(stg + 2 * F_KT_B + dst,  vh + src);
        cp16(stg + 3 * F_KT_B + dst,  vl + src);
    }
    cp_commit();
}

__global__ __launch_bounds__(256, 1) void flash_v2(
    const float* __restrict__ Q,
    const __nv_bfloat16* __restrict__ Khi_g, const __nv_bfloat16* __restrict__ Klo_g,
    const __nv_bfloat16* __restrict__ Vhi_g, const __nv_bfloat16* __restrict__ Vlo_g,
    float* __restrict__ Out)
{
    extern __shared__ __align__(16) char smem_raw[];
    const uint32_t smb  = (uint32_t)__cvta_generic_to_shared(smem_raw);
    const uint32_t q_hi = smb, q_lo = smb + F_QT_B;
    const uint32_t stg0 = smb + 2 * F_QT_B;

    const int tid  = threadIdx.x;
    const int wid  = tid >> 5;
    const int lane = tid & 31;
    const int g    = lane >> 2;
    const int t    = lane & 3;
    const int qb   = gridDim.x - 1 - blockIdx.x;   // big blocks first
    const int h    = blockIdx.y;
    const int kvh  = h >> 2;

    // ---- Q load + split into smem ----
    {
        const float4* Q4 = (const float4*)(Q + ((size_t)h * SEQ + (size_t)qb * 128) * HD);
        __nv_bfloat16* Qh = (__nv_bfloat16*)smem_raw;
        __nv_bfloat16* Ql = (__nv_bfloat16*)(smem_raw + F_QT_B);
        for (int f = tid; f < 4096; f += 256) {
            int row = f >> 5, d0 = (f & 31) << 2;
            float4 q = Q4[f];
            __nv_bfloat16 h0, l0, h1, l1, h2, l2, h3, l3;
            cvt_hl(q.x, h0, l0); cvt_hl(q.y, h1, l1);
            cvt_hl(q.z, h2, l2); cvt_hl(q.w, h3, l3);
            int o = row * LDB + d0;
            *(__nv_bfloat162*)&Qh[o]     = __nv_bfloat162(h0, h1);
            *(__nv_bfloat162*)&Qh[o + 2] = __nv_bfloat162(h2, h3);
            *(__nv_bfloat162*)&Ql[o]     = __nv_bfloat162(l0, l1);
            *(__nv_bfloat162*)&Ql[o + 2] = __nv_bfloat162(l2, l3);
        }
    }

    // ldmatrix lane offsets
    const int a_row = wid * 16 + (lane & 15);
    const int a_col = (lane >> 4) << 3;
    const int kb_row = (lane & 7) + (((lane >> 4) & 1) << 3);   // + 16*jpair
    const int kb_col = ((lane >> 3) & 1) << 3;                  // + 16*ks
    const int v_row  = (lane & 7) + (((lane >> 3) & 1) << 3);   // + 16*kc
    const int v_col  = (lane >> 4) << 3;                        // + 16*jp

    float o_[16][4];
    float m0 = -INFINITY, m1 = -INFINITY, l0 = 0.f, l1 = 0.f;
#pragma unroll
    for (int j = 0; j < 16; j++)
#pragma unroll
        for (int c = 0; c < 4; c++) o_[j][c] = 0.f;

    const float scale = 0.08838834764831845f;
    const int rl0 = wid * 16 + g;       // local q-row (0..127)
    const int rl1 = rl0 + 8;

    const int nkb = 2 * qb + 2;
    f_fill(stg0, Khi_g, Klo_g, Vhi_g, Vlo_g, kvh, 0, tid);

    for (int kb = 0; kb < nkb; kb++) {
        const int buf = kb & 1;
        if (kb + 1 < nkb) {
            f_fill(stg0 + (buf ^ 1) * F_STG_B, Khi_g, Klo_g, Vhi_g, Vlo_g,
                   kvh, kb + 1, tid);
            asm volatile("cp.async.wait_group 1;" ::: "memory");
        } else {
            asm volatile("cp.async.wait_group 0;" ::: "memory");
        }
        __syncthreads();

        const int kofs = kb * 64 - qb * 128;     // key col - q row offset
        if (kofs <= wid * 16 + 15) {             // warp not fully masked
            const uint32_t khi_s = stg0 + buf * F_STG_B;
            const uint32_t klo_s = khi_s + F_KT_B;
            const uint32_t vhi_s = khi_s + 2 * F_KT_B;
            const uint32_t vlo_s = khi_s + 3 * F_KT_B;

            // ---- S = Q K^T (bf16x3) ----
            float sc[8][4];
#pragma unroll
            for (int j = 0; j < 8; j++)
#pragma unroll
                for (int c = 0; c < 4; c++) sc[j][c] = 0.f;

#pragma unroll
            for (int ks = 0; ks < 8; ks++) {
                uint32_t ahf[4], alf[4];
                uint32_t aoff = ((a_row * LDB) + (ks * 16 + a_col)) * 2;
                ldsm4(ahf, q_hi + aoff);
                ldsm4(alf, q_lo + aoff);
#pragma unroll
                for (int jp = 0; jp < 4; jp++) {
                    uint32_t bh[4], bl[4];
                    uint32_t boff = (((jp * 16 + kb_row) * LDB)
                                     + (ks * 16 + kb_col)) * 2;
                    ldsm4(bh, khi_s + boff);
                    ldsm4(bl, klo_s + boff);
                    mma_bf16(sc[2 * jp],     ahf, bh[0], bh[1]);
                    mma_bf16(sc[2 * jp],     ahf, bl[0], bl[1]);
                    mma_bf16(sc[2 * jp],     alf, bh[0], bh[1]);
                    mma_bf16(sc[2 * jp + 1], ahf, bh[2], bh[3]);
                    mma_bf16(sc[2 * jp + 1], ahf, bl[2], bl[3]);
                    mma_bf16(sc[2 * jp + 1], alf, bh[2], bh[3]);
                }
            }

            // ---- mask + online softmax ----
            const bool diag = (kofs + 63 > rl0);
            float tm0 = -INFINITY, tm1 = -INFINITY;
#pragma unroll
            for (int j = 0; j < 8; j++) {
                float v0 = sc[j][0] * scale, v1 = sc[j][1] * scale;
                float v2 = sc[j][2] * scale, v3 = sc[j][3] * scale;
                if (diag) {
                    int c0 = kofs + 8 * j + 2 * t;
                    if (c0     > rl0) v0 = -INFINITY;
                    if (c0 + 1 > rl0) v1 = -INFINITY;
                    if (c0     > rl1) v2 = -INFINITY;
                    if (c0 + 1 > rl1) v3 = -INFINITY;
                }
                sc[j][0] = v0; sc[j][1] = v1; sc[j][2] = v2; sc[j][3] = v3;
                tm0 = fmaxf(tm0, fmaxf(v0, v1));
                tm1 = fmaxf(tm1, fmaxf(v2, v3));
            }
            tm0 = fmaxf(tm0, __shfl_xor_sync(0xffffffffu, tm0, 1));
            tm0 = fmaxf(tm0, __shfl_xor_sync(0xffffffffu, tm0, 2));
            tm1 = fmaxf(tm1, __shfl_xor_sync(0xffffffffu, tm1, 1));
            tm1 = fmaxf(tm1, __shfl_xor_sync(0xffffffffu, tm1, 2));

            float mn0 = fmaxf(m0, tm0), mn1 = fmaxf(m1, tm1);
            float al0 = __expf(m0 - mn0), al1 = __expf(m1 - mn1);
            m0 = mn0; m1 = mn1;

            float rs0 = 0.f, rs1 = 0.f;
#pragma unroll
            for (int j = 0; j < 8; j++) {
                sc[j][0] = __expf(sc[j][0] - mn0);
                sc[j][1] = __expf(sc[j][1] - mn0);
                sc[j][2] = __expf(sc[j][2] - mn1);
                sc[j][3] = __expf(sc[j][3] - mn1);
                rs0 += sc[j][0] + sc[j][1];
                rs1 += sc[j][2] + sc[j][3];
            }
            rs0 += __shfl_xor_sync(0xffffffffu, rs0, 1);
            rs0 += __shfl_xor_sync(0xffffffffu, rs0, 2);
            rs1 += __shfl_xor_sync(0xffffffffu, rs1, 1);
            rs1 += __shfl_xor_sync(0xffffffffu, rs1, 2);
            l0 = l0 * al0 + rs0;
            l1 = l1 * al1 + rs1;

#pragma unroll
            for (int j = 0; j < 16; j++) {
                o_[j][0] *= al0; o_[j][1] *= al0;
                o_[j][2] *= al1; o_[j][3] *= al1;
            }

            uint32_t pah[4][4], pal[4][4];
#pragma unroll
            for (int kc = 0; kc < 4; kc++) {
                int j0 = 2 * kc, j1 = j0 + 1;
                split_pack(sc[j0][0], sc[j0][1], pah[kc][0], pal[kc][0]);
                split_pack(sc[j0][2], sc[j0][3], pah[kc][1], pal[kc][1]);
                split_pack(sc[j1][0], sc[j1][1], pah[kc][2], pal[kc][2]);
                split_pack(sc[j1][2], sc[j1][3], pah[kc][3], pal[kc][3]);
            }

            // ---- O += P V (bf16x3) ----
#pragma unroll
            for (int kc = 0; kc < 4; kc++) {
#pragma unroll
                for (int jp = 0; jp < 8; jp++) {
                    uint32_t vh[4], vl[4];
                    uint32_t voff = (((kc * 16 + v_row) * LDB)
                                     + (jp * 16 + v_col)) * 2;
                    ldsm4t(vh, vhi_s + voff);
                    ldsm4t(vl, vlo_s + voff);
                    mma_bf16(o_[2 * jp],     pah[kc], vh[0], vh[1]);
                    mma_bf16(o_[2 * jp],     pah[kc], vl[0], vl[1]);
                    mma_bf16(o_[2 * jp],     pal[kc], vh[0], vh[1]);
                    mma_bf16(o_[2 * jp + 1], pah[kc], vh[2], vh[3]);
                    mma_bf16(o_[2 * jp + 1], pah[kc], vl[2], vl[3]);
                    mma_bf16(o_[2 * jp + 1], pal[kc], vh[2], vh[3]);
                }
            }
        }
        __syncthreads();
    }

    // ---- write out (tf32-rounded for O-proj) ----
    float inv0 = 1.f / l0, inv1 = 1.f / l1;
    size_t r0 = (size_t)qb * 128 + wid * 16 + g;
    float* base0 = Out + r0 * HID + (size_t)h * HD;
    float* base1 = base0 + (size_t)8 * HID;
#pragma unroll
    for (int j = 0; j < 16; j++) {
        int col = 8 * j + 2 * t;
        *(float2*)(base0 + col) = make_float2(
            __uint_as_float(f2tf32(o_[j][0] * inv0)),
            __uint_as_float(f2tf32(o_[j][1] * inv0)));
        *(float2*)(base1 + col) = make_float2(
            __uint_as_float(f2tf32(o_[j][2] * inv1)),
            __uint_as_float(f2tf32(o_[j][3] * inv1)));
    }
}

// ---------------------------------------------------------------------------
extern "C" void kernel_launch(void* const* d_in, const int* in_sizes, int n_in,
                              void* d_out, int out_size)
{
    const float* Hs = (const float*)d_in[0];
    const float* Wq = (const float*)d_in[1];
    const float* Wk = (const float*)d_in[2];
    const float* Wv = (const float*)d_in[3];
    const float* Wo = (const float*)d_in[4];
    const int*  pos = (const int*)d_in[5];
    float* out = (float*)d_out;

    float *Qp, *Kp, *Vp, *Ap, *rH, *rWq, *rWk, *rWv, *rWo;
    __nv_bfloat16 *Khi, *Klo, *Vhi, *Vlo;
    cudaGetSymbolAddress((void**)&Qp,  g_Q);
    cudaGetSymbolAddress((void**)&Kp,  g_K);
    cudaGetSymbolAddress((void**)&Vp,  g_V);
    cudaGetSymbolAddress((void**)&Ap,  g_A);
    cudaGetSymbolAddress((void**)&rH,  g_rH);
    cudaGetSymbolAddress((void**)&rWq, g_rWq);
    cudaGetSymbolAddress((void**)&rWk, g_rWk);
    cudaGetSymbolAddress((void**)&rWv, g_rWv);
    cudaGetSymbolAddress((void**)&rWo, g_rWo);
    cudaGetSymbolAddress((void**)&Khi, g_Khi);
    cudaGetSymbolAddress((void**)&Klo, g_Klo);
    cudaGetSymbolAddress((void**)&Vhi, g_Vhi);
    cudaGetSymbolAddress((void**)&Vlo, g_Vlo);

    cudaFuncSetAttribute(flash_v2, cudaFuncAttributeMaxDynamicSharedMemorySize,
                         F_SMEM);
    cudaFuncSetAttribute(gemm_tf32_v2, cudaFuncAttributeMaxDynamicSharedMemorySize,
                         G_SMEM);

    // tf32 pre-rounding
    const int nH4 = SEQ * HID / 4, nW4 = HID * HID / 4, nKV4 = NKV * HD * HID / 4;
    round_tf32<<<nH4 / 256, 256>>>((const float4*)Hs, (float4*)rH, nH4);
    round_tf32<<<nW4 / 256, 256>>>((const float4*)Wq, (float4*)rWq, nW4);
    round_tf32<<<nKV4 / 256, 256>>>((const float4*)Wk, (float4*)rWk, nKV4);
    round_tf32<<<nKV4 / 256, 256>>>((const float4*)Wv, (float4*)rWv, nKV4);
    round_tf32<<<nW4 / 256, 256>>>((const float4*)Wo, (float4*)rWo, nW4);

    // projections (tf32 v2), head-major scatter
    gemm_tf32_v2<<<dim3(HID / 256, SEQ / 128), 256, G_SMEM>>>(rH, rWq, Qp,
                                                              SEQ, HID, HID, 1);
    gemm_tf32_v2<<<dim3(NKV * HD / 256, SEQ / 128), 256, G_SMEM>>>(rH, rWk, Kp,
                                                                   SEQ, NKV * HD, HID, 1);
    gemm_tf32_v2<<<dim3(NKV * HD / 256, SEQ / 128), 256, G_SMEM>>>(rH, rWv, Vp,
                                                                   SEQ, NKV * HD, HID, 1);

    // RoPE: Q fp32 in place, K -> split bf16
    rope_kernel<<<((NHEADS + NKV) * SEQ * 64) / 256, 256>>>(Qp, Kp, Khi, Klo, pos);

    // V -> split bf16
    const int nV4 = NKV * SEQ * HD / 4;
    split_kernel<<<nV4 / 256, 256>>>((const float4*)Vp,
        (__nv_bfloat162*)Vhi, (__nv_bfloat162*)Vlo, nV4);

    // causal flash attention v2 -> g_A (tf32-rounded)
    flash_v2<<<dim3(SEQ / 128, NHEADS), 256, F_SMEM>>>(Qp, Khi, Klo, Vhi, Vlo, Ap);

    // output projection -> d_out
    gemm_tf32_v2<<<dim3(HID / 256, SEQ / 128), 256, G_SMEM>>>(Ap, rWo, out,
                                                              SEQ, HID, HID, 0);
}